// round 1
// baseline (speedup 1.0000x reference)
#include <cuda_runtime.h>
#include <cstdint>
#include <cstdio>

// Problem constants
#define B_   2
#define T_   4096
#define C_   1024
#define H_   16
#define D_   64
#define NTOK 8192   // B_*T_

// ---------------------------------------------------------------------------
// Scratch (static device globals; no runtime allocation allowed)
// ---------------------------------------------------------------------------
__device__ float g_qkv[(size_t)NTOK * 3072];          // qkv projection output
__device__ float g_q[(size_t)NTOK * C_];              // [B,H,T,D]
__device__ float g_k[(size_t)NTOK * C_];              // [B,H,T,D]
__device__ float g_v[(size_t)NTOK * C_];              // [B,H,T,D]
__device__ float g_o0[(size_t)B_ * H_ * T_ * D_];          // branch0 out (compact)
__device__ float g_o1[(size_t)B_ * H_ * (T_ / 2) * D_];    // branch1 out
__device__ float g_o2[(size_t)B_ * H_ * (T_ / 4) * D_];    // branch2 out
__device__ float g_l0[B_ * H_ * T_];
__device__ float g_l1[B_ * H_ * (T_ / 2)];
__device__ float g_l2[B_ * H_ * (T_ / 4)];
__device__ float g_y[(size_t)NTOK * C_];              // combined, [B,T, h*D+d]

// ---------------------------------------------------------------------------
// Generic SIMT GEMM: C[M,N] = A[M,K] @ B[K,N] + bias, 128x128x16 tiles,
// 256 threads, 8x8 microtile (split 4+4 rows/cols for conflict-free LDS.128).
// mode 0: plain row-major store to Cmat[M,N]
// mode 1: scatter to [B,H,T,D] layout with scale (used for q/k/v projections)
// ---------------------------------------------------------------------------
__global__ __launch_bounds__(256) void gemm128(
    const float* __restrict__ A, int lda,
    const float* __restrict__ Bm, int N,
    const float* __restrict__ bias,
    float* __restrict__ Cmat,
    int K, int mode, float scale)
{
    __shared__ float As[16][132];   // A tile, transposed: As[k][m], padded
    __shared__ float Bs[16][128];   // B tile: Bs[k][n]

    const int tid = threadIdx.x;
    const int tx = tid & 15, ty = tid >> 4;
    const int m0 = blockIdx.y * 128, n0 = blockIdx.x * 128;

    float acc[8][8];
#pragma unroll
    for (int i = 0; i < 8; i++)
#pragma unroll
        for (int j = 0; j < 8; j++) acc[i][j] = 0.f;

    const int arow = tid >> 2;        // 0..63 (p=1 adds 64)
    const int akc  = (tid & 3) * 4;   // k offset within tile
    const int brow = tid >> 5;        // 0..7  (p=1 adds 8)
    const int bnc  = (tid & 31) * 4;  // n offset within tile

    for (int k0 = 0; k0 < K; k0 += 16) {
#pragma unroll
        for (int p = 0; p < 2; p++) {
            int row = arow + p * 64;
            float4 av = *(const float4*)&A[(size_t)(m0 + row) * lda + k0 + akc];
            As[akc + 0][row] = av.x;
            As[akc + 1][row] = av.y;
            As[akc + 2][row] = av.z;
            As[akc + 3][row] = av.w;
            int kr = brow + p * 8;
            *(float4*)&Bs[kr][bnc] =
                *(const float4*)&Bm[(size_t)(k0 + kr) * N + n0 + bnc];
        }
        __syncthreads();
#pragma unroll
        for (int k = 0; k < 16; k++) {
            float a[8], b[8];
            *(float4*)&a[0] = *(const float4*)&As[k][ty * 4];
            *(float4*)&a[4] = *(const float4*)&As[k][64 + ty * 4];
            *(float4*)&b[0] = *(const float4*)&Bs[k][tx * 4];
            *(float4*)&b[4] = *(const float4*)&Bs[k][64 + tx * 4];
#pragma unroll
            for (int i = 0; i < 8; i++)
#pragma unroll
                for (int j = 0; j < 8; j++)
                    acc[i][j] = fmaf(a[i], b[j], acc[i][j]);
        }
        __syncthreads();
    }

    // Epilogue
#pragma unroll
    for (int ic = 0; ic < 2; ic++)
#pragma unroll
        for (int ii = 0; ii < 4; ii++) {
            int r = m0 + ic * 64 + ty * 4 + ii;
#pragma unroll
            for (int jc = 0; jc < 2; jc++) {
                int c = n0 + jc * 64 + tx * 4;
                float4 o;
                o.x = (acc[ic * 4 + ii][jc * 4 + 0] + bias[c + 0]) * scale;
                o.y = (acc[ic * 4 + ii][jc * 4 + 1] + bias[c + 1]) * scale;
                o.z = (acc[ic * 4 + ii][jc * 4 + 2] + bias[c + 2]) * scale;
                o.w = (acc[ic * 4 + ii][jc * 4 + 3] + bias[c + 3]) * scale;
                if (mode == 0) {
                    *(float4*)&Cmat[(size_t)r * N + c] = o;
                } else {
                    int b = r >> 12, t = r & 4095;   // T_ = 4096
                    int h = c >> 6, d = c & 63;      // D_ = 64
                    *(float4*)&Cmat[(((size_t)(b * H_ + h) * T_) + t) * D_ + d] = o;
                }
            }
        }
}

// ---------------------------------------------------------------------------
// Dilated causal attention, one branch. CTA = (m_tile of 128 queries, seg, bh).
// eff = 512 always. Gathered positions: t = seg*w + (h & (r-1)) + j*r.
// Flash-style online softmax over 128-wide key tiles; P staged in smem for PV.
// Writes compact branch output o[bh, seg*512 + j, d] and lse.
// ---------------------------------------------------------------------------
#define ATTN_SMEM_FLOATS (64 * 132 * 2 + 128 * 68 + 128 * 132)

__global__ __launch_bounds__(256) void attn_kernel(
    const float* __restrict__ q, const float* __restrict__ k,
    const float* __restrict__ v,
    float* __restrict__ obr, float* __restrict__ lbr,
    int w, int r, int Tr)
{
    extern __shared__ float sm[];
    float* Qt = sm;                 // [64][132] : Qt[d][row]
    float* Kt = Qt + 64 * 132;      // [64][132] : Kt[d][row]
    float* Vs = Kt + 64 * 132;      // [128][68] : Vs[row][d]
    float* Ps = Vs + 128 * 68;      // [128][132]: Ps[row][col]

    const int tid = threadIdx.x;
    const int tx = tid & 15, ty = tid >> 4;
    const int m0 = blockIdx.x * 128;
    const int seg = blockIdx.y;
    const int bh = blockIdx.z;
    const int h = bh & (H_ - 1);
    const int off = h & (r - 1);
    const size_t qbase = (size_t)bh * T_;
    const int segbase = seg * w + off;

    // Row indices owned by this thread (split 4+4)
    int Rrow[8];
#pragma unroll
    for (int i = 0; i < 8; i++)
        Rrow[i] = (i < 4) ? (ty * 4 + i) : (64 + ty * 4 + (i - 4));

    // Load Q tile (transposed into smem)
#pragma unroll
    for (int p = 0; p < 8; p++) {
        int f = tid + p * 256;
        int row = f >> 4;
        int d4 = (f & 15) * 4;
        int t = segbase + (m0 + row) * r;
        float4 qv = *(const float4*)&q[(qbase + t) * D_ + d4];
        Qt[(d4 + 0) * 132 + row] = qv.x;
        Qt[(d4 + 1) * 132 + row] = qv.y;
        Qt[(d4 + 2) * 132 + row] = qv.z;
        Qt[(d4 + 3) * 132 + row] = qv.w;
    }

    float mI[8], lI[8], acc[8][4];
#pragma unroll
    for (int i = 0; i < 8; i++) {
        mI[i] = -1e30f;
        lI[i] = 0.f;
        acc[i][0] = acc[i][1] = acc[i][2] = acc[i][3] = 0.f;
    }

    const int ntile = (m0 >> 7) + 1;
    for (int nt = 0; nt < ntile; nt++) {
        const int n0 = nt * 128;
        __syncthreads();   // protect Kt/Vs/Ps from previous iteration

        // Load K (transposed) and V tiles
#pragma unroll
        for (int p = 0; p < 8; p++) {
            int f = tid + p * 256;
            int row = f >> 4;
            int d4 = (f & 15) * 4;
            int t = segbase + (n0 + row) * r;
            size_t gidx = (qbase + t) * D_ + d4;
            float4 kv = *(const float4*)&k[gidx];
            Kt[(d4 + 0) * 132 + row] = kv.x;
            Kt[(d4 + 1) * 132 + row] = kv.y;
            Kt[(d4 + 2) * 132 + row] = kv.z;
            Kt[(d4 + 3) * 132 + row] = kv.w;
            *(float4*)&Vs[row * 68 + d4] = *(const float4*)&v[gidx];
        }
        __syncthreads();

        // S = Q K^T  (q pre-scaled by D^-0.5)
        float S[8][8];
#pragma unroll
        for (int i = 0; i < 8; i++)
#pragma unroll
            for (int j = 0; j < 8; j++) S[i][j] = 0.f;

#pragma unroll 8
        for (int d = 0; d < 64; d++) {
            float a[8], b[8];
            *(float4*)&a[0] = *(const float4*)&Qt[d * 132 + ty * 4];
            *(float4*)&a[4] = *(const float4*)&Qt[d * 132 + 64 + ty * 4];
            *(float4*)&b[0] = *(const float4*)&Kt[d * 132 + tx * 4];
            *(float4*)&b[4] = *(const float4*)&Kt[d * 132 + 64 + tx * 4];
#pragma unroll
            for (int i = 0; i < 8; i++)
#pragma unroll
                for (int j = 0; j < 8; j++)
                    S[i][j] = fmaf(a[i], b[j], S[i][j]);
        }

        // Causal mask (only the diagonal tile needs it)
        if (n0 == m0) {
#pragma unroll
            for (int i = 0; i < 8; i++) {
                int Rg = Rrow[i];
#pragma unroll
                for (int j = 0; j < 8; j++) {
                    int Cg = (j < 4) ? (tx * 4 + j) : (64 + tx * 4 + (j - 4));
                    if (Cg > Rg) S[i][j] = -1e30f;
                }
            }
        }

        // Online softmax (row reductions across the 16 tx lanes)
#pragma unroll
        for (int i = 0; i < 8; i++) {
            float rmax = S[i][0];
#pragma unroll
            for (int j = 1; j < 8; j++) rmax = fmaxf(rmax, S[i][j]);
            rmax = fmaxf(rmax, __shfl_xor_sync(0xffffffffu, rmax, 8));
            rmax = fmaxf(rmax, __shfl_xor_sync(0xffffffffu, rmax, 4));
            rmax = fmaxf(rmax, __shfl_xor_sync(0xffffffffu, rmax, 2));
            rmax = fmaxf(rmax, __shfl_xor_sync(0xffffffffu, rmax, 1));
            float mn = fmaxf(mI[i], rmax);
            float alpha = __expf(mI[i] - mn);
            mI[i] = mn;
            float rs = 0.f;
#pragma unroll
            for (int j = 0; j < 8; j++) {
                float pv = __expf(S[i][j] - mn);
                S[i][j] = pv;
                rs += pv;
            }
            rs += __shfl_xor_sync(0xffffffffu, rs, 8);
            rs += __shfl_xor_sync(0xffffffffu, rs, 4);
            rs += __shfl_xor_sync(0xffffffffu, rs, 2);
            rs += __shfl_xor_sync(0xffffffffu, rs, 1);
            lI[i] = lI[i] * alpha + rs;
            acc[i][0] *= alpha;
            acc[i][1] *= alpha;
            acc[i][2] *= alpha;
            acc[i][3] *= alpha;
        }

        // Stage P into smem
#pragma unroll
        for (int i = 0; i < 8; i++) {
            int Rg = Rrow[i];
            *(float4*)&Ps[Rg * 132 + tx * 4] =
                make_float4(S[i][0], S[i][1], S[i][2], S[i][3]);
            *(float4*)&Ps[Rg * 132 + 64 + tx * 4] =
                make_float4(S[i][4], S[i][5], S[i][6], S[i][7]);
        }
        __syncthreads();

        // O += P V
#pragma unroll 4
        for (int j = 0; j < 128; j++) {
            float4 vv = *(const float4*)&Vs[j * 68 + tx * 4];
#pragma unroll
            for (int i = 0; i < 8; i++) {
                float pv = Ps[Rrow[i] * 132 + j];
                acc[i][0] = fmaf(pv, vv.x, acc[i][0]);
                acc[i][1] = fmaf(pv, vv.y, acc[i][1]);
                acc[i][2] = fmaf(pv, vv.z, acc[i][2]);
                acc[i][3] = fmaf(pv, vv.w, acc[i][3]);
            }
        }
    }

    // Epilogue: normalize and write compact branch output + lse
#pragma unroll
    for (int i = 0; i < 8; i++) {
        int Rg = Rrow[i];
        float inv = 1.f / lI[i];
        float4 o = make_float4(acc[i][0] * inv, acc[i][1] * inv,
                               acc[i][2] * inv, acc[i][3] * inv);
        size_t orow = (size_t)bh * Tr + seg * 512 + m0 + Rg;
        *(float4*)&obr[orow * D_ + tx * 4] = o;
        if (tx == 0) lbr[orow] = mI[i] + logf(lI[i]);
    }
}

// ---------------------------------------------------------------------------
// Combine branches with LSE softmax weights; write y in [b, t, h*D+d] layout.
// Coverage: branch1 iff t%2==h%2 ; branch2 iff t%4==h%4 ; branch0 always.
// ---------------------------------------------------------------------------
__global__ __launch_bounds__(128) void combine_kernel(
    const float* __restrict__ o0, const float* __restrict__ o1,
    const float* __restrict__ o2,
    const float* __restrict__ l0, const float* __restrict__ l1,
    const float* __restrict__ l2,
    float* __restrict__ y)
{
    int rowid = blockIdx.x * 128 + threadIdx.x;   // (bh, t)
    int bh = rowid >> 12;
    int t = rowid & 4095;
    int h = bh & (H_ - 1);
    int b = bh >> 4;

    float L0 = l0[(size_t)bh * 4096 + t];
    bool c1 = ((t & 1) == (h & 1));
    bool c2 = ((t & 3) == (h & 3));
    size_t i1 = (size_t)bh * 2048 + ((size_t)(t >> 10) << 9) + ((t & 1023) >> 1);
    size_t i2 = (size_t)bh * 1024 + ((size_t)(t >> 11) << 9) + ((t & 2047) >> 2);
    float L1 = c1 ? l1[i1] : -1e30f;
    float L2 = c2 ? l2[i2] : -1e30f;
    float m = fmaxf(L0, fmaxf(L1, L2));
    float w0 = __expf(L0 - m);
    float w1 = c1 ? __expf(L1 - m) : 0.f;
    float w2 = c2 ? __expf(L2 - m) : 0.f;
    float inv = 1.f / (w0 + w1 + w2);
    w0 *= inv; w1 *= inv; w2 *= inv;

    const float* p0 = o0 + ((size_t)bh * 4096 + t) * D_;
    const float* p1 = o1 + i1 * D_;
    const float* p2 = o2 + i2 * D_;
    float* yo = y + ((size_t)(b * 4096 + t)) * C_ + h * D_;

#pragma unroll
    for (int d = 0; d < 64; d += 4) {
        float4 a0 = *(const float4*)&p0[d];
        float4 res = make_float4(w0 * a0.x, w0 * a0.y, w0 * a0.z, w0 * a0.w);
        if (c1) {
            float4 a1 = *(const float4*)&p1[d];
            res.x += w1 * a1.x; res.y += w1 * a1.y;
            res.z += w1 * a1.z; res.w += w1 * a1.w;
        }
        if (c2) {
            float4 a2 = *(const float4*)&p2[d];
            res.x += w2 * a2.x; res.y += w2 * a2.y;
            res.z += w2 * a2.z; res.w += w2 * a2.w;
        }
        *(float4*)&yo[d] = res;
    }
}

// ---------------------------------------------------------------------------
// Launch
// ---------------------------------------------------------------------------
extern "C" void kernel_launch(void* const* d_in, const int* in_sizes, int n_in,
                              void* d_out, int out_size)
{
    (void)in_sizes; (void)n_in; (void)out_size;
    const float* x        = (const float*)d_in[0];
    const float* c_attn_w = (const float*)d_in[1];
    const float* c_attn_b = (const float*)d_in[2];
    const float* q_w      = (const float*)d_in[3];
    const float* q_b      = (const float*)d_in[4];
    const float* k_w      = (const float*)d_in[5];
    const float* k_b      = (const float*)d_in[6];
    const float* v_w      = (const float*)d_in[7];
    const float* v_b      = (const float*)d_in[8];
    const float* o_w      = (const float*)d_in[9];
    const float* o_b      = (const float*)d_in[10];
    float* out = (float*)d_out;

    float *qkv, *qp, *kp, *vp, *o0, *o1, *o2, *l0, *l1, *l2, *y;
    cudaGetSymbolAddress((void**)&qkv, g_qkv);
    cudaGetSymbolAddress((void**)&qp,  g_q);
    cudaGetSymbolAddress((void**)&kp,  g_k);
    cudaGetSymbolAddress((void**)&vp,  g_v);
    cudaGetSymbolAddress((void**)&o0,  g_o0);
    cudaGetSymbolAddress((void**)&o1,  g_o1);
    cudaGetSymbolAddress((void**)&o2,  g_o2);
    cudaGetSymbolAddress((void**)&l0,  g_l0);
    cudaGetSymbolAddress((void**)&l1,  g_l1);
    cudaGetSymbolAddress((void**)&l2,  g_l2);
    cudaGetSymbolAddress((void**)&y,   g_y);

    const size_t attn_smem = (size_t)ATTN_SMEM_FLOATS * sizeof(float); // ~166 KB
    cudaFuncSetAttribute(attn_kernel,
                         cudaFuncAttributeMaxDynamicSharedMemorySize,
                         (int)attn_smem);

    dim3 blk(256);

    // 1) qkv = x @ c_attn_w + c_attn_b           [8192,3072]
    gemm128<<<dim3(24, 64), blk>>>(x, C_, c_attn_w, 3 * C_, c_attn_b,
                                   qkv, C_, 0, 1.f);
    // 2) q/k/v projections, scattered to [B,H,T,D]; q pre-scaled by D^-0.5
    gemm128<<<dim3(8, 64), blk>>>(qkv + 0,        3 * C_, q_w, C_, q_b,
                                  qp, C_, 1, 0.125f);
    gemm128<<<dim3(8, 64), blk>>>(qkv + C_,       3 * C_, k_w, C_, k_b,
                                  kp, C_, 1, 1.f);
    gemm128<<<dim3(8, 64), blk>>>(qkv + 2 * C_,   3 * C_, v_w, C_, v_b,
                                  vp, C_, 1, 1.f);
    // 3) three dilated-attention branches
    attn_kernel<<<dim3(4, 8, B_ * H_), 256, attn_smem>>>(qp, kp, vp, o0, l0,
                                                         512, 1, 4096);
    attn_kernel<<<dim3(4, 4, B_ * H_), 256, attn_smem>>>(qp, kp, vp, o1, l1,
                                                         1024, 2, 2048);
    attn_kernel<<<dim3(4, 2, B_ * H_), 256, attn_smem>>>(qp, kp, vp, o2, l2,
                                                         2048, 4, 1024);
    // 4) LSE-weighted combine -> y [8192, 1024]
    combine_kernel<<<dim3(B_ * H_ * T_ / 128), 128>>>(o0, o1, o2, l0, l1, l2, y);
    // 5) out = y @ o_w + o_b
    gemm128<<<dim3(8, 64), blk>>>(y, C_, o_w, C_, o_b, out, C_, 0, 1.f);
}

// round 5
// speedup vs baseline: 1.6988x; 1.6988x over previous
#include <cuda_runtime.h>
#include <cuda_bf16.h>
#include <cstdint>

// Problem constants
#define B_   2
#define T_   4096
#define C_   1024
#define H_   16
#define D_   64
#define NTOK 8192   // B_*T_

// ---------------------------------------------------------------------------
// Scratch (static device globals; no runtime allocation allowed)
// ---------------------------------------------------------------------------
__device__ __nv_bfloat16 g_xs  [(size_t)NTOK * 2048];   // x split  [hi|lo]
__device__ __nv_bfloat16 g_qkvs[(size_t)NTOK * 6144];   // qkv split [hi(3072)|lo(3072)]
__device__ __nv_bfloat16 g_wc  [(size_t)3072 * 2048];   // c_attn_w^T split [N, 2K]
__device__ __nv_bfloat16 g_wq  [(size_t)1024 * 2048];
__device__ __nv_bfloat16 g_wk  [(size_t)1024 * 2048];
__device__ __nv_bfloat16 g_wv  [(size_t)1024 * 2048];
__device__ __nv_bfloat16 g_wo  [(size_t)1024 * 2048];
__device__ float g_q[(size_t)NTOK * C_];                // [B,H,T,D] fp32
__device__ float g_k[(size_t)NTOK * C_];
__device__ float g_v[(size_t)NTOK * C_];
__device__ float g_o0[(size_t)B_ * H_ * T_ * D_];
__device__ float g_o1[(size_t)B_ * H_ * (T_ / 2) * D_];
__device__ float g_o2[(size_t)B_ * H_ * (T_ / 4) * D_];
__device__ float g_l0[B_ * H_ * T_];
__device__ float g_l1[B_ * H_ * (T_ / 2)];
__device__ float g_l2[B_ * H_ * (T_ / 4)];
__device__ __nv_bfloat16 g_y2[(size_t)NTOK * 2048];     // combined split [hi|lo]

// ---------------------------------------------------------------------------
// PTX helpers (base sm_103 target: mma.sync / ldmatrix / cp.async only)
// ---------------------------------------------------------------------------
__device__ __forceinline__ uint32_t smem_u32(const void* p) {
    uint32_t a;
    asm("{ .reg .u64 t; cvta.to.shared.u64 t, %1; cvt.u32.u64 %0, t; }"
        : "=r"(a) : "l"(p));
    return a;
}
__device__ __forceinline__ void cp16(uint32_t dst, const void* src) {
    asm volatile("cp.async.cg.shared.global [%0], [%1], 16;\n"
                 :: "r"(dst), "l"(src));
}
__device__ __forceinline__ void ldm4(uint32_t* r, uint32_t a) {
    asm volatile("ldmatrix.sync.aligned.m8n8.x4.shared.b16 {%0,%1,%2,%3}, [%4];"
                 : "=r"(r[0]), "=r"(r[1]), "=r"(r[2]), "=r"(r[3]) : "r"(a));
}
__device__ __forceinline__ void mma16816(float* c, const uint32_t* a,
                                         const uint32_t* b) {
    asm volatile(
        "mma.sync.aligned.m16n8k16.row.col.f32.bf16.bf16.f32 "
        "{%0,%1,%2,%3}, {%4,%5,%6,%7}, {%8,%9}, {%0,%1,%2,%3};"
        : "+f"(c[0]), "+f"(c[1]), "+f"(c[2]), "+f"(c[3])
        : "r"(a[0]), "r"(a[1]), "r"(a[2]), "r"(a[3]), "r"(b[0]), "r"(b[1]));
}

// ---------------------------------------------------------------------------
// Split-bf16 HMMA GEMM: C[M,N] = A[M,K] @ W[K,N] + bias (fp32 accuracy via
// 3-term bf16 split fused along K: hi*hi + hi*lo + lo*hi).
// A : split bf16 [M, lda], hi cols at aHi.., lo at aLo..   (K-major)
// Bt: W^T split bf16 [N, ldb], hi at bHi, lo at bLo        (K-major)
// CTA tile 128x128, 8 warps (32x64 each), K-chunk = 32 bf16, 4-stage cp.async.
// smem pitch 80B per 32-element row -> conflict-free ldmatrix (banks 20r mod 32).
// mode 0: fp32 store out[row*ldc + n]
// mode 1: fp32 scatter to [B,H,T,D] with scale (q/k/v)
// mode 2: split-bf16 store: hi at out[row*ldc + oHi + n], lo at +oLo
// ---------------------------------------------------------------------------
#define STAGEB 20480              // (128*80)*2 tiles per stage
#define GEMM_SMEM (4 * STAGEB)    // 81920 B

__global__ __launch_bounds__(256) void gemm_mma(
    const __nv_bfloat16* __restrict__ A, int lda, int aHi, int aLo,
    const __nv_bfloat16* __restrict__ Bt, int ldb, int bHi, int bLo,
    const float* __restrict__ bias, void* __restrict__ outp,
    int ldc, int oHi, int oLo, int NKC, int mode, float scale)
{
    extern __shared__ __align__(128) char smx[];
    const uint32_t su = smem_u32(smx);
    const int tid = threadIdx.x;
    const int warp = tid >> 5, lane = tid & 31;
    const int wm = warp >> 1, wn = warp & 1;
    const int m0 = blockIdx.y * 128, n0 = blockIdx.x * 128;
    const int NC = 3 * NKC;

    float acc[2][8][4];
#pragma unroll
    for (int i = 0; i < 2; i++)
#pragma unroll
        for (int j = 0; j < 8; j++)
#pragma unroll
            for (int q = 0; q < 4; q++) acc[i][j][q] = 0.f;

    auto loads = [&](int c, int s) {
        int ka, kb;
        if (c < NKC)            { ka = aHi + c * 32;            kb = bHi + c * 32; }
        else if (c < 2 * NKC)   { int k2 = c - NKC;     ka = aHi + k2 * 32; kb = bLo + k2 * 32; }
        else                    { int k2 = c - 2 * NKC; ka = aLo + k2 * 32; kb = bHi + k2 * 32; }
        uint32_t sa = su + (uint32_t)s * STAGEB;
        uint32_t sb = sa + 10240;
#pragma unroll
        for (int j = 0; j < 2; j++) {
            int f = tid + j * 256;
            int r = f >> 2, si = (f & 3) * 16;
            cp16(sa + r * 80 + si,
                 (const char*)(A + (size_t)(m0 + r) * lda + ka) + si);
            cp16(sb + r * 80 + si,
                 (const char*)(Bt + (size_t)(n0 + r) * ldb + kb) + si);
        }
        asm volatile("cp.async.commit_group;\n" ::: "memory");
    };

    loads(0, 0); loads(1, 1); loads(2, 2);

#pragma unroll 1
    for (int c = 0; c < NC; c++) {
        asm volatile("cp.async.wait_group 2;\n" ::: "memory");
        __syncthreads();
        if (c + 3 < NC) loads(c + 3, (c + 3) & 3);

        uint32_t sa = su + (uint32_t)(c & 3) * STAGEB;
        uint32_t sb = sa + 10240;
#pragma unroll
        for (int kk = 0; kk < 2; kk++) {
            uint32_t af[2][4];
#pragma unroll
            for (int mm = 0; mm < 2; mm++) {
                uint32_t addr = sa +
                    (uint32_t)(wm * 32 + mm * 16 + (lane & 15)) * 80 +
                    ((lane >> 4) << 4) + kk * 32;
                ldm4(af[mm], addr);
            }
            uint32_t bf[4][4];
#pragma unroll
            for (int nb = 0; nb < 4; nb++) {
                int rown = wn * 64 + nb * 16 + ((lane >> 4) & 1) * 8 + (lane & 7);
                uint32_t addr = sb + (uint32_t)rown * 80 +
                    (((lane >> 3) & 1) << 4) + kk * 32;
                ldm4(bf[nb], addr);
            }
#pragma unroll
            for (int mm = 0; mm < 2; mm++)
#pragma unroll
                for (int nn = 0; nn < 8; nn++)
                    mma16816(acc[mm][nn], af[mm], &bf[nn >> 1][(nn & 1) * 2]);
        }
    }

    // Epilogue (accumulators in registers)
    const int r0 = m0 + wm * 32 + (lane >> 2);
    const int c0b = n0 + wn * 64 + (lane & 3) * 2;
#pragma unroll
    for (int mm = 0; mm < 2; mm++)
#pragma unroll
        for (int nn = 0; nn < 8; nn++) {
            float* cc = acc[mm][nn];
            int col = c0b + nn * 8;
#pragma unroll
            for (int hf = 0; hf < 2; hf++) {
                int row = r0 + mm * 16 + hf * 8;
                float v0 = cc[hf * 2 + 0] + bias[col];
                float v1 = cc[hf * 2 + 1] + bias[col + 1];
                if (mode == 0) {
                    float2 o; o.x = v0; o.y = v1;
                    *(float2*)((float*)outp + (size_t)row * ldc + col) = o;
                } else if (mode == 1) {
                    v0 *= scale; v1 *= scale;
                    int bI = row >> 12, t = row & 4095;
                    int h = col >> 6, d = col & 63;
                    float2 o; o.x = v0; o.y = v1;
                    *(float2*)((float*)outp +
                               (((size_t)(bI * H_ + h) * T_) + t) * D_ + d) = o;
                } else {
                    __nv_bfloat16 h0 = __float2bfloat16(v0);
                    __nv_bfloat16 h1 = __float2bfloat16(v1);
                    __nv_bfloat162 hv, lv;
                    hv.x = h0; hv.y = h1;
                    lv.x = __float2bfloat16(v0 - __bfloat162float(h0));
                    lv.y = __float2bfloat16(v1 - __bfloat162float(h1));
                    __nv_bfloat16* ob = (__nv_bfloat16*)outp;
                    size_t rb = (size_t)row * ldc;
                    *(__nv_bfloat162*)&ob[rb + oHi + col] = hv;
                    *(__nv_bfloat162*)&ob[rb + oLo + col] = lv;
                }
            }
        }
}

// ---------------------------------------------------------------------------
// Weight transpose + split: W[K,N] fp32 -> Wt[N, 2K] bf16 (hi at k, lo at K+k)
// ---------------------------------------------------------------------------
__global__ __launch_bounds__(256) void wsplitT(
    const float* __restrict__ W, int K, int N, __nv_bfloat16* __restrict__ Wt)
{
    __shared__ float tile[32][33];
    int n0 = blockIdx.x * 32, k0 = blockIdx.y * 32;
    int tx = threadIdx.x, ty = threadIdx.y;   // 32 x 8
#pragma unroll
    for (int i = 0; i < 32; i += 8)
        tile[ty + i][tx] = W[(size_t)(k0 + ty + i) * N + n0 + tx];
    __syncthreads();
#pragma unroll
    for (int i = 0; i < 32; i += 8) {
        int n = n0 + ty + i, k = k0 + tx;
        float v = tile[tx][ty + i];
        __nv_bfloat16 h = __float2bfloat16(v);
        Wt[(size_t)n * 2 * K + k] = h;
        Wt[(size_t)n * 2 * K + K + k] = __float2bfloat16(v - __bfloat162float(h));
    }
}

// x[8192,1024] fp32 -> xs[8192,2048] bf16 split
__global__ __launch_bounds__(256) void xsplit(
    const float* __restrict__ x, __nv_bfloat16* __restrict__ xs)
{
    size_t i = (size_t)blockIdx.x * 256 + threadIdx.x;   // one float4 each
    size_t r = i >> 8;
    int c = (int)(i & 255) * 4;
    float4 v = *(const float4*)&x[r * 1024 + c];
    __nv_bfloat162 h0, h1, l0, l1;
    h0.x = __float2bfloat16(v.x); h0.y = __float2bfloat16(v.y);
    h1.x = __float2bfloat16(v.z); h1.y = __float2bfloat16(v.w);
    l0.x = __float2bfloat16(v.x - __bfloat162float(h0.x));
    l0.y = __float2bfloat16(v.y - __bfloat162float(h0.y));
    l1.x = __float2bfloat16(v.z - __bfloat162float(h1.x));
    l1.y = __float2bfloat16(v.w - __bfloat162float(h1.y));
    *(__nv_bfloat162*)&xs[r * 2048 + c] = h0;
    *(__nv_bfloat162*)&xs[r * 2048 + c + 2] = h1;
    *(__nv_bfloat162*)&xs[r * 2048 + 1024 + c] = l0;
    *(__nv_bfloat162*)&xs[r * 2048 + 1024 + c + 2] = l1;
}

// ---------------------------------------------------------------------------
// Dilated causal attention (fp32 SIMT, unchanged from R1 — passes at 1e-6)
// ---------------------------------------------------------------------------
#define ATTN_SMEM_FLOATS (64 * 132 * 2 + 128 * 68 + 128 * 132)

__global__ __launch_bounds__(256) void attn_kernel(
    const float* __restrict__ q, const float* __restrict__ k,
    const float* __restrict__ v,
    float* __restrict__ obr, float* __restrict__ lbr,
    int w, int r, int Tr)
{
    extern __shared__ float sm[];
    float* Qt = sm;
    float* Kt = Qt + 64 * 132;
    float* Vs = Kt + 64 * 132;
    float* Ps = Vs + 128 * 68;

    const int tid = threadIdx.x;
    const int tx = tid & 15, ty = tid >> 4;
    const int m0 = blockIdx.x * 128;
    const int seg = blockIdx.y;
    const int bh = blockIdx.z;
    const int h = bh & (H_ - 1);
    const int off = h & (r - 1);
    const size_t qbase = (size_t)bh * T_;
    const int segbase = seg * w + off;

    int Rrow[8];
#pragma unroll
    for (int i = 0; i < 8; i++)
        Rrow[i] = (i < 4) ? (ty * 4 + i) : (64 + ty * 4 + (i - 4));

#pragma unroll
    for (int p = 0; p < 8; p++) {
        int f = tid + p * 256;
        int row = f >> 4;
        int d4 = (f & 15) * 4;
        int t = segbase + (m0 + row) * r;
        float4 qv = *(const float4*)&q[(qbase + t) * D_ + d4];
        Qt[(d4 + 0) * 132 + row] = qv.x;
        Qt[(d4 + 1) * 132 + row] = qv.y;
        Qt[(d4 + 2) * 132 + row] = qv.z;
        Qt[(d4 + 3) * 132 + row] = qv.w;
    }

    float mI[8], lI[8], acc[8][4];
#pragma unroll
    for (int i = 0; i < 8; i++) {
        mI[i] = -1e30f;
        lI[i] = 0.f;
        acc[i][0] = acc[i][1] = acc[i][2] = acc[i][3] = 0.f;
    }

    const int ntile = (m0 >> 7) + 1;
    for (int nt = 0; nt < ntile; nt++) {
        const int n0 = nt * 128;
        __syncthreads();

#pragma unroll
        for (int p = 0; p < 8; p++) {
            int f = tid + p * 256;
            int row = f >> 4;
            int d4 = (f & 15) * 4;
            int t = segbase + (n0 + row) * r;
            size_t gidx = (qbase + t) * D_ + d4;
            float4 kv = *(const float4*)&k[gidx];
            Kt[(d4 + 0) * 132 + row] = kv.x;
            Kt[(d4 + 1) * 132 + row] = kv.y;
            Kt[(d4 + 2) * 132 + row] = kv.z;
            Kt[(d4 + 3) * 132 + row] = kv.w;
            *(float4*)&Vs[row * 68 + d4] = *(const float4*)&v[gidx];
        }
        __syncthreads();

        float S[8][8];
#pragma unroll
        for (int i = 0; i < 8; i++)
#pragma unroll
            for (int j = 0; j < 8; j++) S[i][j] = 0.f;

#pragma unroll 8
        for (int d = 0; d < 64; d++) {
            float a[8], b[8];
            *(float4*)&a[0] = *(const float4*)&Qt[d * 132 + ty * 4];
            *(float4*)&a[4] = *(const float4*)&Qt[d * 132 + 64 + ty * 4];
            *(float4*)&b[0] = *(const float4*)&Kt[d * 132 + tx * 4];
            *(float4*)&b[4] = *(const float4*)&Kt[d * 132 + 64 + tx * 4];
#pragma unroll
            for (int i = 0; i < 8; i++)
#pragma unroll
                for (int j = 0; j < 8; j++)
                    S[i][j] = fmaf(a[i], b[j], S[i][j]);
        }

        if (n0 == m0) {
#pragma unroll
            for (int i = 0; i < 8; i++) {
                int Rg = Rrow[i];
#pragma unroll
                for (int j = 0; j < 8; j++) {
                    int Cg = (j < 4) ? (tx * 4 + j) : (64 + tx * 4 + (j - 4));
                    if (Cg > Rg) S[i][j] = -1e30f;
                }
            }
        }

#pragma unroll
        for (int i = 0; i < 8; i++) {
            float rmax = S[i][0];
#pragma unroll
            for (int j = 1; j < 8; j++) rmax = fmaxf(rmax, S[i][j]);
            rmax = fmaxf(rmax, __shfl_xor_sync(0xffffffffu, rmax, 8));
            rmax = fmaxf(rmax, __shfl_xor_sync(0xffffffffu, rmax, 4));
            rmax = fmaxf(rmax, __shfl_xor_sync(0xffffffffu, rmax, 2));
            rmax = fmaxf(rmax, __shfl_xor_sync(0xffffffffu, rmax, 1));
            float mn = fmaxf(mI[i], rmax);
            float alpha = __expf(mI[i] - mn);
            mI[i] = mn;
            float rs = 0.f;
#pragma unroll
            for (int j = 0; j < 8; j++) {
                float pv = __expf(S[i][j] - mn);
                S[i][j] = pv;
                rs += pv;
            }
            rs += __shfl_xor_sync(0xffffffffu, rs, 8);
            rs += __shfl_xor_sync(0xffffffffu, rs, 4);
            rs += __shfl_xor_sync(0xffffffffu, rs, 2);
            rs += __shfl_xor_sync(0xffffffffu, rs, 1);
            lI[i] = lI[i] * alpha + rs;
            acc[i][0] *= alpha;
            acc[i][1] *= alpha;
            acc[i][2] *= alpha;
            acc[i][3] *= alpha;
        }

#pragma unroll
        for (int i = 0; i < 8; i++) {
            int Rg = Rrow[i];
            *(float4*)&Ps[Rg * 132 + tx * 4] =
                make_float4(S[i][0], S[i][1], S[i][2], S[i][3]);
            *(float4*)&Ps[Rg * 132 + 64 + tx * 4] =
                make_float4(S[i][4], S[i][5], S[i][6], S[i][7]);
        }
        __syncthreads();

#pragma unroll 4
        for (int j = 0; j < 128; j++) {
            float4 vv = *(const float4*)&Vs[j * 68 + tx * 4];
#pragma unroll
            for (int i = 0; i < 8; i++) {
                float pv = Ps[Rrow[i] * 132 + j];
                acc[i][0] = fmaf(pv, vv.x, acc[i][0]);
                acc[i][1] = fmaf(pv, vv.y, acc[i][1]);
                acc[i][2] = fmaf(pv, vv.z, acc[i][2]);
                acc[i][3] = fmaf(pv, vv.w, acc[i][3]);
            }
        }
    }

#pragma unroll
    for (int i = 0; i < 8; i++) {
        int Rg = Rrow[i];
        float inv = 1.f / lI[i];
        float4 o = make_float4(acc[i][0] * inv, acc[i][1] * inv,
                               acc[i][2] * inv, acc[i][3] * inv);
        size_t orow = (size_t)bh * Tr + seg * 512 + m0 + Rg;
        *(float4*)&obr[orow * D_ + tx * 4] = o;
        if (tx == 0) lbr[orow] = mI[i] + logf(lI[i]);
    }
}

// ---------------------------------------------------------------------------
// Combine branches with LSE weights; emit split bf16 y2 [8192, 2048]
// ---------------------------------------------------------------------------
__global__ __launch_bounds__(128) void combine_kernel(
    const float* __restrict__ o0, const float* __restrict__ o1,
    const float* __restrict__ o2,
    const float* __restrict__ l0, const float* __restrict__ l1,
    const float* __restrict__ l2,
    __nv_bfloat16* __restrict__ y2)
{
    int rowid = blockIdx.x * 128 + threadIdx.x;   // (bh, t)
    int bh = rowid >> 12;
    int t = rowid & 4095;
    int h = bh & (H_ - 1);
    int b = bh >> 4;

    float L0 = l0[(size_t)bh * 4096 + t];
    bool c1 = ((t & 1) == (h & 1));
    bool c2 = ((t & 3) == (h & 3));
    size_t i1 = (size_t)bh * 2048 + ((size_t)(t >> 10) << 9) + ((t & 1023) >> 1);
    size_t i2 = (size_t)bh * 1024 + ((size_t)(t >> 11) << 9) + ((t & 2047) >> 2);
    float L1 = c1 ? l1[i1] : -1e30f;
    float L2 = c2 ? l2[i2] : -1e30f;
    float m = fmaxf(L0, fmaxf(L1, L2));
    float w0 = __expf(L0 - m);
    float w1 = c1 ? __expf(L1 - m) : 0.f;
    float w2 = c2 ? __expf(L2 - m) : 0.f;
    float inv = 1.f / (w0 + w1 + w2);
    w0 *= inv; w1 *= inv; w2 *= inv;

    const float* p0 = o0 + ((size_t)bh * 4096 + t) * D_;
    const float* p1 = o1 + i1 * D_;
    const float* p2 = o2 + i2 * D_;
    size_t ybase = (size_t)(b * 4096 + t) * 2048 + h * D_;

#pragma unroll
    for (int d = 0; d < 64; d += 4) {
        float4 a0 = *(const float4*)&p0[d];
        float4 res = make_float4(w0 * a0.x, w0 * a0.y, w0 * a0.z, w0 * a0.w);
        if (c1) {
            float4 a1 = *(const float4*)&p1[d];
            res.x += w1 * a1.x; res.y += w1 * a1.y;
            res.z += w1 * a1.z; res.w += w1 * a1.w;
        }
        if (c2) {
            float4 a2 = *(const float4*)&p2[d];
            res.x += w2 * a2.x; res.y += w2 * a2.y;
            res.z += w2 * a2.z; res.w += w2 * a2.w;
        }
        __nv_bfloat162 h0, h1, lo0, lo1;
        h0.x = __float2bfloat16(res.x); h0.y = __float2bfloat16(res.y);
        h1.x = __float2bfloat16(res.z); h1.y = __float2bfloat16(res.w);
        lo0.x = __float2bfloat16(res.x - __bfloat162float(h0.x));
        lo0.y = __float2bfloat16(res.y - __bfloat162float(h0.y));
        lo1.x = __float2bfloat16(res.z - __bfloat162float(h1.x));
        lo1.y = __float2bfloat16(res.w - __bfloat162float(h1.y));
        *(__nv_bfloat162*)&y2[ybase + d] = h0;
        *(__nv_bfloat162*)&y2[ybase + d + 2] = h1;
        *(__nv_bfloat162*)&y2[ybase + 1024 + d] = lo0;
        *(__nv_bfloat162*)&y2[ybase + 1024 + d + 2] = lo1;
    }
}

// ---------------------------------------------------------------------------
// Launch
// ---------------------------------------------------------------------------
extern "C" void kernel_launch(void* const* d_in, const int* in_sizes, int n_in,
                              void* d_out, int out_size)
{
    (void)in_sizes; (void)n_in; (void)out_size;
    const float* x        = (const float*)d_in[0];
    const float* c_attn_w = (const float*)d_in[1];
    const float* c_attn_b = (const float*)d_in[2];
    const float* q_w      = (const float*)d_in[3];
    const float* q_b      = (const float*)d_in[4];
    const float* k_w      = (const float*)d_in[5];
    const float* k_b      = (const float*)d_in[6];
    const float* v_w      = (const float*)d_in[7];
    const float* v_b      = (const float*)d_in[8];
    const float* o_w      = (const float*)d_in[9];
    const float* o_b      = (const float*)d_in[10];
    float* out = (float*)d_out;

    __nv_bfloat16 *xs, *qkvs, *wc, *wq, *wk, *wv, *wo, *y2;
    float *qp, *kp, *vp, *o0, *o1, *o2, *l0, *l1, *l2;
    cudaGetSymbolAddress((void**)&xs,   g_xs);
    cudaGetSymbolAddress((void**)&qkvs, g_qkvs);
    cudaGetSymbolAddress((void**)&wc,   g_wc);
    cudaGetSymbolAddress((void**)&wq,   g_wq);
    cudaGetSymbolAddress((void**)&wk,   g_wk);
    cudaGetSymbolAddress((void**)&wv,   g_wv);
    cudaGetSymbolAddress((void**)&wo,   g_wo);
    cudaGetSymbolAddress((void**)&y2,   g_y2);
    cudaGetSymbolAddress((void**)&qp,   g_q);
    cudaGetSymbolAddress((void**)&kp,   g_k);
    cudaGetSymbolAddress((void**)&vp,   g_v);
    cudaGetSymbolAddress((void**)&o0,   g_o0);
    cudaGetSymbolAddress((void**)&o1,   g_o1);
    cudaGetSymbolAddress((void**)&o2,   g_o2);
    cudaGetSymbolAddress((void**)&l0,   g_l0);
    cudaGetSymbolAddress((void**)&l1,   g_l1);
    cudaGetSymbolAddress((void**)&l2,   g_l2);

    cudaFuncSetAttribute(gemm_mma, cudaFuncAttributeMaxDynamicSharedMemorySize,
                         GEMM_SMEM);
    const size_t attn_smem = (size_t)ATTN_SMEM_FLOATS * sizeof(float);
    cudaFuncSetAttribute(attn_kernel,
                         cudaFuncAttributeMaxDynamicSharedMemorySize,
                         (int)attn_smem);

    // 0) conversions: weight transpose+split, activation split
    wsplitT<<<dim3(96, 32), dim3(32, 8)>>>(c_attn_w, 1024, 3072, wc);
    wsplitT<<<dim3(32, 32), dim3(32, 8)>>>(q_w, 1024, 1024, wq);
    wsplitT<<<dim3(32, 32), dim3(32, 8)>>>(k_w, 1024, 1024, wk);
    wsplitT<<<dim3(32, 32), dim3(32, 8)>>>(v_w, 1024, 1024, wv);
    wsplitT<<<dim3(32, 32), dim3(32, 8)>>>(o_w, 1024, 1024, wo);
    xsplit<<<8192, 256>>>(x, xs);

    // 1) qkv = x @ c_attn_w + b  -> split bf16 [8192, 6144]
    gemm_mma<<<dim3(24, 64), 256, GEMM_SMEM>>>(
        xs, 2048, 0, 1024, wc, 2048, 0, 1024, c_attn_b,
        qkvs, 6144, 0, 3072, 32, 2, 1.f);
    // 2) q/k/v projections -> fp32 [B,H,T,D]; q pre-scaled
    gemm_mma<<<dim3(8, 64), 256, GEMM_SMEM>>>(
        qkvs, 6144, 0, 3072, wq, 2048, 0, 1024, q_b,
        qp, 0, 0, 0, 32, 1, 0.125f);
    gemm_mma<<<dim3(8, 64), 256, GEMM_SMEM>>>(
        qkvs, 6144, 1024, 4096, wk, 2048, 0, 1024, k_b,
        kp, 0, 0, 0, 32, 1, 1.f);
    gemm_mma<<<dim3(8, 64), 256, GEMM_SMEM>>>(
        qkvs, 6144, 2048, 5120, wv, 2048, 0, 1024, v_b,
        vp, 0, 0, 0, 32, 1, 1.f);
    // 3) dilated attention branches (fp32)
    attn_kernel<<<dim3(4, 8, B_ * H_), 256, attn_smem>>>(qp, kp, vp, o0, l0,
                                                         512, 1, 4096);
    attn_kernel<<<dim3(4, 4, B_ * H_), 256, attn_smem>>>(qp, kp, vp, o1, l1,
                                                         1024, 2, 2048);
    attn_kernel<<<dim3(4, 2, B_ * H_), 256, attn_smem>>>(qp, kp, vp, o2, l2,
                                                         2048, 4, 1024);
    // 4) combine -> split bf16 y2
    combine_kernel<<<dim3(B_ * H_ * T_ / 128), 128>>>(o0, o1, o2, l0, l1, l2,
                                                      y2);
    // 5) out = y @ o_w + o_b  (fp32 to d_out)
    gemm_mma<<<dim3(8, 64), 256, GEMM_SMEM>>>(
        y2, 2048, 0, 1024, wo, 2048, 0, 1024, o_b,
        out, 1024, 0, 0, 32, 0, 1.f);
}

// round 7
// speedup vs baseline: 2.0042x; 1.1798x over previous
#include <cuda_runtime.h>
#include <cuda_bf16.h>
#include <cstdint>

// Problem constants
#define B_   2
#define T_   4096
#define C_   1024
#define H_   16
#define D_   64
#define NTOK 8192   // B_*T_

// ---------------------------------------------------------------------------
// Scratch (static device globals; no runtime allocation allowed)
// ---------------------------------------------------------------------------
__device__ __nv_bfloat16 g_xs  [(size_t)NTOK * 2048];   // x split [hi|lo]
__device__ __nv_bfloat16 g_wq  [(size_t)1024 * 2048];   // Wq^T split
__device__ __nv_bfloat16 g_wk  [(size_t)1024 * 2048];
__device__ __nv_bfloat16 g_wv  [(size_t)1024 * 2048];
__device__ __nv_bfloat16 g_wo  [(size_t)1024 * 2048];
__device__ __nv_bfloat16 g_wcr [(size_t)3 * 1024 * 2048]; // Wc slices row-split
__device__ __nv_bfloat16 g_wf  [(size_t)3072 * 2048];   // fused W^T split [n,2k]
__device__ float g_bf[3072];                            // fused biases
__device__ float g_zero[1024];                          // zero bias (static 0)
__device__ float g_qkvp[(size_t)3 * NTOK * C_];         // q/k/v [s][B,H,T,D] fp32
__device__ float g_o0[(size_t)B_ * H_ * T_ * D_];
__device__ float g_o1[(size_t)B_ * H_ * (T_ / 2) * D_];
__device__ float g_o2[(size_t)B_ * H_ * (T_ / 4) * D_];
__device__ float g_l0[B_ * H_ * T_];
__device__ float g_l1[B_ * H_ * (T_ / 2)];
__device__ float g_l2[B_ * H_ * (T_ / 4)];
__device__ __nv_bfloat16 g_y2[(size_t)NTOK * 2048];     // combined split [hi|lo]

// ---------------------------------------------------------------------------
// PTX helpers (base sm_103 target: mma.sync / ldmatrix / cp.async only)
// ---------------------------------------------------------------------------
__device__ __forceinline__ uint32_t smem_u32(const void* p) {
    uint32_t a;
    asm("{ .reg .u64 t; cvta.to.shared.u64 t, %1; cvt.u32.u64 %0, t; }"
        : "=r"(a) : "l"(p));
    return a;
}
__device__ __forceinline__ void cp16(uint32_t dst, const void* src) {
    asm volatile("cp.async.cg.shared.global [%0], [%1], 16;\n"
                 :: "r"(dst), "l"(src));
}
__device__ __forceinline__ void ldm4(uint32_t* r, uint32_t a) {
    asm volatile("ldmatrix.sync.aligned.m8n8.x4.shared.b16 {%0,%1,%2,%3}, [%4];"
                 : "=r"(r[0]), "=r"(r[1]), "=r"(r[2]), "=r"(r[3]) : "r"(a));
}
__device__ __forceinline__ void mma16816(float* c, const uint32_t* a,
                                         const uint32_t* b) {
    asm volatile(
        "mma.sync.aligned.m16n8k16.row.col.f32.bf16.bf16.f32 "
        "{%0,%1,%2,%3}, {%4,%5,%6,%7}, {%8,%9}, {%0,%1,%2,%3};"
        : "+f"(c[0]), "+f"(c[1]), "+f"(c[2]), "+f"(c[3])
        : "r"(a[0]), "r"(a[1]), "r"(a[2]), "r"(a[3]), "r"(b[0]), "r"(b[1]));
}

// ---------------------------------------------------------------------------
// Split-bf16 HMMA GEMM: C[M,N] = A[M,K] @ W[K,N] + bias (fp32 accuracy via
// 3-term bf16 split fused along K: hi*hi + hi*lo + lo*hi).
// A : split bf16 [M, lda], hi cols at aHi.., lo at aLo..   (K-major)
// Bt: W^T split bf16 [N, ldb], hi at bHi, lo at bLo        (K-major)
// CTA tile 128x128, 8 warps (32x64 each), K-chunk = 32 bf16, 4-stage cp.async.
// smem pitch 80B per 32-element row -> conflict-free ldmatrix.
// mode 0: fp32 store out[row*ldc + n]
// mode 1: fp32 scatter of merged qkv to [s][B,H,T,D]; s==0 scaled by `scale`
// mode 3: transposed split store (fused-weight prep): out[col*ldc + {0,oLo} + row]
// ---------------------------------------------------------------------------
#define STAGEB 20480              // (128*80)*2 tiles per stage
#define GEMM_SMEM (4 * STAGEB)    // 81920 B

__global__ __launch_bounds__(256) void gemm_mma(
    const __nv_bfloat16* __restrict__ A, int lda, int aHi, int aLo,
    const __nv_bfloat16* __restrict__ Bt, int ldb, int bHi, int bLo,
    const float* __restrict__ bias, void* __restrict__ outp,
    int ldc, int oLo, int NKC, int mode, float scale)
{
    extern __shared__ __align__(128) char smx[];
    const uint32_t su = smem_u32(smx);
    const int tid = threadIdx.x;
    const int warp = tid >> 5, lane = tid & 31;
    const int wm = warp >> 1, wn = warp & 1;
    const int m0 = blockIdx.y * 128, n0 = blockIdx.x * 128;
    const int NC = 3 * NKC;

    float acc[2][8][4];
#pragma unroll
    for (int i = 0; i < 2; i++)
#pragma unroll
        for (int j = 0; j < 8; j++)
#pragma unroll
            for (int q = 0; q < 4; q++) acc[i][j][q] = 0.f;

    auto loads = [&](int c, int s) {
        int ka, kb;
        if (c < NKC)            { ka = aHi + c * 32;            kb = bHi + c * 32; }
        else if (c < 2 * NKC)   { int k2 = c - NKC;     ka = aHi + k2 * 32; kb = bLo + k2 * 32; }
        else                    { int k2 = c - 2 * NKC; ka = aLo + k2 * 32; kb = bHi + k2 * 32; }
        uint32_t sa = su + (uint32_t)s * STAGEB;
        uint32_t sb = sa + 10240;
#pragma unroll
        for (int j = 0; j < 2; j++) {
            int f = tid + j * 256;
            int r = f >> 2, si = (f & 3) * 16;
            cp16(sa + r * 80 + si,
                 (const char*)(A + (size_t)(m0 + r) * lda + ka) + si);
            cp16(sb + r * 80 + si,
                 (const char*)(Bt + (size_t)(n0 + r) * ldb + kb) + si);
        }
        asm volatile("cp.async.commit_group;\n" ::: "memory");
    };

    loads(0, 0); loads(1, 1); loads(2, 2);

#pragma unroll 1
    for (int c = 0; c < NC; c++) {
        asm volatile("cp.async.wait_group 2;\n" ::: "memory");
        __syncthreads();
        if (c + 3 < NC) loads(c + 3, (c + 3) & 3);

        uint32_t sa = su + (uint32_t)(c & 3) * STAGEB;
        uint32_t sb = sa + 10240;
#pragma unroll
        for (int kk = 0; kk < 2; kk++) {
            uint32_t af[2][4];
#pragma unroll
            for (int mm = 0; mm < 2; mm++) {
                uint32_t addr = sa +
                    (uint32_t)(wm * 32 + mm * 16 + (lane & 15)) * 80 +
                    ((lane >> 4) << 4) + kk * 32;
                ldm4(af[mm], addr);
            }
            uint32_t bf[4][4];
#pragma unroll
            for (int nb = 0; nb < 4; nb++) {
                int rown = wn * 64 + nb * 16 + ((lane >> 4) & 1) * 8 + (lane & 7);
                uint32_t addr = sb + (uint32_t)rown * 80 +
                    (((lane >> 3) & 1) << 4) + kk * 32;
                ldm4(bf[nb], addr);
            }
#pragma unroll
            for (int mm = 0; mm < 2; mm++)
#pragma unroll
                for (int nn = 0; nn < 8; nn++)
                    mma16816(acc[mm][nn], af[mm], &bf[nn >> 1][(nn & 1) * 2]);
        }
    }

    // Epilogue (accumulators in registers)
    const int r0 = m0 + wm * 32 + (lane >> 2);
    const int c0b = n0 + wn * 64 + (lane & 3) * 2;
#pragma unroll
    for (int mm = 0; mm < 2; mm++)
#pragma unroll
        for (int nn = 0; nn < 8; nn++) {
            float* cc = acc[mm][nn];
            int col = c0b + nn * 8;
#pragma unroll
            for (int hf = 0; hf < 2; hf++) {
                int row = r0 + mm * 16 + hf * 8;
                float v0 = cc[hf * 2 + 0] + bias[col];
                float v1 = cc[hf * 2 + 1] + bias[col + 1];
                if (mode == 0) {
                    float2 o; o.x = v0; o.y = v1;
                    *(float2*)((float*)outp + (size_t)row * ldc + col) = o;
                } else if (mode == 1) {
                    int s = col >> 10;
                    int c1 = col & 1023;
                    int h = c1 >> 6, d = c1 & 63;
                    float sc = (s == 0) ? scale : 1.f;
                    v0 *= sc; v1 *= sc;
                    int bI = row >> 12, t = row & 4095;
                    float2 o; o.x = v0; o.y = v1;
                    *(float2*)((float*)outp +
                               (size_t)s * ((size_t)NTOK * C_) +
                               (((size_t)(bI * H_ + h) * T_) + t) * D_ + d) = o;
                } else {   // mode 3: transposed split (fused weight prep)
                    __nv_bfloat16* ob = (__nv_bfloat16*)outp;
                    __nv_bfloat16 h0 = __float2bfloat16(v0);
                    ob[(size_t)col * ldc + row] = h0;
                    ob[(size_t)col * ldc + oLo + row] =
                        __float2bfloat16(v0 - __bfloat162float(h0));
                    __nv_bfloat16 h1 = __float2bfloat16(v1);
                    ob[(size_t)(col + 1) * ldc + row] = h1;
                    ob[(size_t)(col + 1) * ldc + oLo + row] =
                        __float2bfloat16(v1 - __bfloat162float(h1));
                }
            }
        }
}

// ---------------------------------------------------------------------------
// Weight transpose + split: W[K,N] fp32 -> Wt[N, 2K] bf16 (hi at k, lo at K+k)
// ---------------------------------------------------------------------------
__global__ __launch_bounds__(256) void wsplitT(
    const float* __restrict__ W, int K, int N, __nv_bfloat16* __restrict__ Wt)
{
    __shared__ float tile[32][33];
    int n0 = blockIdx.x * 32, k0 = blockIdx.y * 32;
    int tx = threadIdx.x, ty = threadIdx.y;   // 32 x 8
#pragma unroll
    for (int i = 0; i < 32; i += 8)
        tile[ty + i][tx] = W[(size_t)(k0 + ty + i) * N + n0 + tx];
    __syncthreads();
#pragma unroll
    for (int i = 0; i < 32; i += 8) {
        int n = n0 + ty + i, k = k0 + tx;
        float v = tile[tx][ty + i];
        __nv_bfloat16 h = __float2bfloat16(v);
        Wt[(size_t)n * 2 * K + k] = h;
        Wt[(size_t)n * 2 * K + K + k] = __float2bfloat16(v - __bfloat162float(h));
    }
}

// Row-major split of a submatrix: out[i, k]=hi, out[i, K+k]=lo of
// W[i*ldw + colOff + k], i < rows (one CTA per row), K = 1024.
__global__ __launch_bounds__(256) void rowsplit(
    const float* __restrict__ W, int ldw, int colOff,
    __nv_bfloat16* __restrict__ out)
{
    int i = blockIdx.x;
    int c = threadIdx.x * 4;
    float4 v = *(const float4*)&W[(size_t)i * ldw + colOff + c];
    __nv_bfloat162 h0, h1, l0, l1;
    h0.x = __float2bfloat16(v.x); h0.y = __float2bfloat16(v.y);
    h1.x = __float2bfloat16(v.z); h1.y = __float2bfloat16(v.w);
    l0.x = __float2bfloat16(v.x - __bfloat162float(h0.x));
    l0.y = __float2bfloat16(v.y - __bfloat162float(h0.y));
    l1.x = __float2bfloat16(v.z - __bfloat162float(h1.x));
    l1.y = __float2bfloat16(v.w - __bfloat162float(h1.y));
    __nv_bfloat16* o = out + (size_t)i * 2048;
    *(__nv_bfloat162*)&o[c] = h0;
    *(__nv_bfloat162*)&o[c + 2] = h1;
    *(__nv_bfloat162*)&o[1024 + c] = l0;
    *(__nv_bfloat162*)&o[1024 + c + 2] = l1;
}

// x[8192,1024] fp32 -> xs[8192,2048] bf16 split
__global__ __launch_bounds__(256) void xsplit(
    const float* __restrict__ x, __nv_bfloat16* __restrict__ xs)
{
    size_t i = (size_t)blockIdx.x * 256 + threadIdx.x;   // one float4 each
    size_t r = i >> 8;
    int c = (int)(i & 255) * 4;
    float4 v = *(const float4*)&x[r * 1024 + c];
    __nv_bfloat162 h0, h1, l0, l1;
    h0.x = __float2bfloat16(v.x); h0.y = __float2bfloat16(v.y);
    h1.x = __float2bfloat16(v.z); h1.y = __float2bfloat16(v.w);
    l0.x = __float2bfloat16(v.x - __bfloat162float(h0.x));
    l0.y = __float2bfloat16(v.y - __bfloat162float(h0.y));
    l1.x = __float2bfloat16(v.z - __bfloat162float(h1.x));
    l1.y = __float2bfloat16(v.w - __bfloat162float(h1.y));
    *(__nv_bfloat162*)&xs[r * 2048 + c] = h0;
    *(__nv_bfloat162*)&xs[r * 2048 + c + 2] = h1;
    *(__nv_bfloat162*)&xs[r * 2048 + 1024 + c] = l0;
    *(__nv_bfloat162*)&xs[r * 2048 + 1024 + c + 2] = l1;
}

// Fused bias: out[s*1024 + n] = sum_m bc[s*1024+m] * Ws[m*1024+n] + b2s[n]
__global__ __launch_bounds__(1024) void biasfold3(
    const float* __restrict__ bc,
    const float* __restrict__ Wq, const float* __restrict__ Wk,
    const float* __restrict__ Wv,
    const float* __restrict__ bq, const float* __restrict__ bk,
    const float* __restrict__ bv,
    float* __restrict__ out)
{
    int s = blockIdx.x;
    int n = threadIdx.x;
    const float* W  = (s == 0) ? Wq : (s == 1) ? Wk : Wv;
    const float* b2 = (s == 0) ? bq : (s == 1) ? bk : bv;
    const float* bs = bc + s * 1024;
    float a0 = 0.f, a1 = 0.f, a2 = 0.f, a3 = 0.f;
#pragma unroll 1
    for (int m = 0; m < 1024; m += 16) {
#pragma unroll
        for (int j = 0; j < 16; j++) {
            float w = W[(size_t)(m + j) * 1024 + n];
            float bb = bs[m + j];
            if ((j & 3) == 0) a0 = fmaf(bb, w, a0);
            else if ((j & 3) == 1) a1 = fmaf(bb, w, a1);
            else if ((j & 3) == 2) a2 = fmaf(bb, w, a2);
            else a3 = fmaf(bb, w, a3);
        }
    }
    out[s * 1024 + n] = a0 + a1 + a2 + a3 + b2[n];
}

// ---------------------------------------------------------------------------
// Dilated causal attention (fp32 SIMT — passes at 1e-6)
// ---------------------------------------------------------------------------
#define ATTN_SMEM_FLOATS (64 * 132 * 2 + 128 * 68 + 128 * 132)

__global__ __launch_bounds__(256) void attn_kernel(
    const float* __restrict__ q, const float* __restrict__ k,
    const float* __restrict__ v,
    float* __restrict__ obr, float* __restrict__ lbr,
    int w, int r, int Tr)
{
    extern __shared__ float sm[];
    float* Qt = sm;
    float* Kt = Qt + 64 * 132;
    float* Vs = Kt + 64 * 132;
    float* Ps = Vs + 128 * 68;

    const int tid = threadIdx.x;
    const int tx = tid & 15, ty = tid >> 4;
    const int m0 = blockIdx.x * 128;
    const int seg = blockIdx.y;
    const int bh = blockIdx.z;
    const int h = bh & (H_ - 1);
    const int off = h & (r - 1);
    const size_t qbase = (size_t)bh * T_;
    const int segbase = seg * w + off;

    int Rrow[8];
#pragma unroll
    for (int i = 0; i < 8; i++)
        Rrow[i] = (i < 4) ? (ty * 4 + i) : (64 + ty * 4 + (i - 4));

#pragma unroll
    for (int p = 0; p < 8; p++) {
        int f = tid + p * 256;
        int row = f >> 4;
        int d4 = (f & 15) * 4;
        int t = segbase + (m0 + row) * r;
        float4 qv = *(const float4*)&q[(qbase + t) * D_ + d4];
        Qt[(d4 + 0) * 132 + row] = qv.x;
        Qt[(d4 + 1) * 132 + row] = qv.y;
        Qt[(d4 + 2) * 132 + row] = qv.z;
        Qt[(d4 + 3) * 132 + row] = qv.w;
    }

    float mI[8], lI[8], acc[8][4];
#pragma unroll
    for (int i = 0; i < 8; i++) {
        mI[i] = -1e30f;
        lI[i] = 0.f;
        acc[i][0] = acc[i][1] = acc[i][2] = acc[i][3] = 0.f;
    }

    const int ntile = (m0 >> 7) + 1;
    for (int nt = 0; nt < ntile; nt++) {
        const int n0 = nt * 128;
        __syncthreads();

#pragma unroll
        for (int p = 0; p < 8; p++) {
            int f = tid + p * 256;
            int row = f >> 4;
            int d4 = (f & 15) * 4;
            int t = segbase + (n0 + row) * r;
            size_t gidx = (qbase + t) * D_ + d4;
            float4 kv = *(const float4*)&k[gidx];
            Kt[(d4 + 0) * 132 + row] = kv.x;
            Kt[(d4 + 1) * 132 + row] = kv.y;
            Kt[(d4 + 2) * 132 + row] = kv.z;
            Kt[(d4 + 3) * 132 + row] = kv.w;
            *(float4*)&Vs[row * 68 + d4] = *(const float4*)&v[gidx];
        }
        __syncthreads();

        float S[8][8];
#pragma unroll
        for (int i = 0; i < 8; i++)
#pragma unroll
            for (int j = 0; j < 8; j++) S[i][j] = 0.f;

#pragma unroll 8
        for (int d = 0; d < 64; d++) {
            float a[8], b[8];
            *(float4*)&a[0] = *(const float4*)&Qt[d * 132 + ty * 4];
            *(float4*)&a[4] = *(const float4*)&Qt[d * 132 + 64 + ty * 4];
            *(float4*)&b[0] = *(const float4*)&Kt[d * 132 + tx * 4];
            *(float4*)&b[4] = *(const float4*)&Kt[d * 132 + 64 + tx * 4];
#pragma unroll
            for (int i = 0; i < 8; i++)
#pragma unroll
                for (int j = 0; j < 8; j++)
                    S[i][j] = fmaf(a[i], b[j], S[i][j]);
        }

        if (n0 == m0) {
#pragma unroll
            for (int i = 0; i < 8; i++) {
                int Rg = Rrow[i];
#pragma unroll
                for (int j = 0; j < 8; j++) {
                    int Cg = (j < 4) ? (tx * 4 + j) : (64 + tx * 4 + (j - 4));
                    if (Cg > Rg) S[i][j] = -1e30f;
                }
            }
        }

#pragma unroll
        for (int i = 0; i < 8; i++) {
            float rmax = S[i][0];
#pragma unroll
            for (int j = 1; j < 8; j++) rmax = fmaxf(rmax, S[i][j]);
            rmax = fmaxf(rmax, __shfl_xor_sync(0xffffffffu, rmax, 8));
            rmax = fmaxf(rmax, __shfl_xor_sync(0xffffffffu, rmax, 4));
            rmax = fmaxf(rmax, __shfl_xor_sync(0xffffffffu, rmax, 2));
            rmax = fmaxf(rmax, __shfl_xor_sync(0xffffffffu, rmax, 1));
            float mn = fmaxf(mI[i], rmax);
            float alpha = __expf(mI[i] - mn);
            mI[i] = mn;
            float rs = 0.f;
#pragma unroll
            for (int j = 0; j < 8; j++) {
                float pv = __expf(S[i][j] - mn);
                S[i][j] = pv;
                rs += pv;
            }
            rs += __shfl_xor_sync(0xffffffffu, rs, 8);
            rs += __shfl_xor_sync(0xffffffffu, rs, 4);
            rs += __shfl_xor_sync(0xffffffffu, rs, 2);
            rs += __shfl_xor_sync(0xffffffffu, rs, 1);
            lI[i] = lI[i] * alpha + rs;
            acc[i][0] *= alpha;
            acc[i][1] *= alpha;
            acc[i][2] *= alpha;
            acc[i][3] *= alpha;
        }

#pragma unroll
        for (int i = 0; i < 8; i++) {
            int Rg = Rrow[i];
            *(float4*)&Ps[Rg * 132 + tx * 4] =
                make_float4(S[i][0], S[i][1], S[i][2], S[i][3]);
            *(float4*)&Ps[Rg * 132 + 64 + tx * 4] =
                make_float4(S[i][4], S[i][5], S[i][6], S[i][7]);
        }
        __syncthreads();

#pragma unroll 4
        for (int j = 0; j < 128; j++) {
            float4 vv = *(const float4*)&Vs[j * 68 + tx * 4];
#pragma unroll
            for (int i = 0; i < 8; i++) {
                float pv = Ps[Rrow[i] * 132 + j];
                acc[i][0] = fmaf(pv, vv.x, acc[i][0]);
                acc[i][1] = fmaf(pv, vv.y, acc[i][1]);
                acc[i][2] = fmaf(pv, vv.z, acc[i][2]);
                acc[i][3] = fmaf(pv, vv.w, acc[i][3]);
            }
        }
    }

#pragma unroll
    for (int i = 0; i < 8; i++) {
        int Rg = Rrow[i];
        float inv = 1.f / lI[i];
        float4 o = make_float4(acc[i][0] * inv, acc[i][1] * inv,
                               acc[i][2] * inv, acc[i][3] * inv);
        size_t orow = (size_t)bh * Tr + seg * 512 + m0 + Rg;
        *(float4*)&obr[orow * D_ + tx * 4] = o;
        if (tx == 0) lbr[orow] = mI[i] + logf(lI[i]);
    }
}

// ---------------------------------------------------------------------------
// Combine branches with LSE weights; emit split bf16 y2 [8192, 2048]
// ---------------------------------------------------------------------------
__global__ __launch_bounds__(128) void combine_kernel(
    const float* __restrict__ o0, const float* __restrict__ o1,
    const float* __restrict__ o2,
    const float* __restrict__ l0, const float* __restrict__ l1,
    const float* __restrict__ l2,
    __nv_bfloat16* __restrict__ y2)
{
    int rowid = blockIdx.x * 128 + threadIdx.x;   // (bh, t)
    int bh = rowid >> 12;
    int t = rowid & 4095;
    int h = bh & (H_ - 1);
    int b = bh >> 4;

    float L0 = l0[(size_t)bh * 4096 + t];
    bool c1 = ((t & 1) == (h & 1));
    bool c2 = ((t & 3) == (h & 3));
    size_t i1 = (size_t)bh * 2048 + ((size_t)(t >> 10) << 9) + ((t & 1023) >> 1);
    size_t i2 = (size_t)bh * 1024 + ((size_t)(t >> 11) << 9) + ((t & 2047) >> 2);
    float L1 = c1 ? l1[i1] : -1e30f;
    float L2 = c2 ? l2[i2] : -1e30f;
    float m = fmaxf(L0, fmaxf(L1, L2));
    float w0 = __expf(L0 - m);
    float w1 = c1 ? __expf(L1 - m) : 0.f;
    float w2 = c2 ? __expf(L2 - m) : 0.f;
    float inv = 1.f / (w0 + w1 + w2);
    w0 *= inv; w1 *= inv; w2 *= inv;

    const float* p0 = o0 + ((size_t)bh * 4096 + t) * D_;
    const float* p1 = o1 + i1 * D_;
    const float* p2 = o2 + i2 * D_;
    size_t ybase = (size_t)(b * 4096 + t) * 2048 + h * D_;

#pragma unroll
    for (int d = 0; d < 64; d += 4) {
        float4 a0 = *(const float4*)&p0[d];
        float4 res = make_float4(w0 * a0.x, w0 * a0.y, w0 * a0.z, w0 * a0.w);
        if (c1) {
            float4 a1 = *(const float4*)&p1[d];
            res.x += w1 * a1.x; res.y += w1 * a1.y;
            res.z += w1 * a1.z; res.w += w1 * a1.w;
        }
        if (c2) {
            float4 a2 = *(const float4*)&p2[d];
            res.x += w2 * a2.x; res.y += w2 * a2.y;
            res.z += w2 * a2.z; res.w += w2 * a2.w;
        }
        __nv_bfloat162 h0, h1, lo0, lo1;
        h0.x = __float2bfloat16(res.x); h0.y = __float2bfloat16(res.y);
        h1.x = __float2bfloat16(res.z); h1.y = __float2bfloat16(res.w);
        lo0.x = __float2bfloat16(res.x - __bfloat162float(h0.x));
        lo0.y = __float2bfloat16(res.y - __bfloat162float(h0.y));
        lo1.x = __float2bfloat16(res.z - __bfloat162float(h1.x));
        lo1.y = __float2bfloat16(res.w - __bfloat162float(h1.y));
        *(__nv_bfloat162*)&y2[ybase + d] = h0;
        *(__nv_bfloat162*)&y2[ybase + d + 2] = h1;
        *(__nv_bfloat162*)&y2[ybase + 1024 + d] = lo0;
        *(__nv_bfloat162*)&y2[ybase + 1024 + d + 2] = lo1;
    }
}

// ---------------------------------------------------------------------------
// Launch
// ---------------------------------------------------------------------------
extern "C" void kernel_launch(void* const* d_in, const int* in_sizes, int n_in,
                              void* d_out, int out_size)
{
    (void)in_sizes; (void)n_in; (void)out_size;
    const float* x        = (const float*)d_in[0];
    const float* c_attn_w = (const float*)d_in[1];
    const float* c_attn_b = (const float*)d_in[2];
    const float* q_w      = (const float*)d_in[3];
    const float* q_b      = (const float*)d_in[4];
    const float* k_w      = (const float*)d_in[5];
    const float* k_b      = (const float*)d_in[6];
    const float* v_w      = (const float*)d_in[7];
    const float* v_b      = (const float*)d_in[8];
    const float* o_w      = (const float*)d_in[9];
    const float* o_b      = (const float*)d_in[10];
    float* out = (float*)d_out;

    __nv_bfloat16 *xs, *wq, *wk, *wv, *wo, *wcr, *wf, *y2;
    float *bf, *zero, *qkvp, *o0, *o1, *o2, *l0, *l1, *l2;
    cudaGetSymbolAddress((void**)&xs,   g_xs);
    cudaGetSymbolAddress((void**)&wq,   g_wq);
    cudaGetSymbolAddress((void**)&wk,   g_wk);
    cudaGetSymbolAddress((void**)&wv,   g_wv);
    cudaGetSymbolAddress((void**)&wo,   g_wo);
    cudaGetSymbolAddress((void**)&wcr,  g_wcr);
    cudaGetSymbolAddress((void**)&wf,   g_wf);
    cudaGetSymbolAddress((void**)&bf,   g_bf);
    cudaGetSymbolAddress((void**)&zero, g_zero);
    cudaGetSymbolAddress((void**)&qkvp, g_qkvp);
    cudaGetSymbolAddress((void**)&y2,   g_y2);
    cudaGetSymbolAddress((void**)&o0,   g_o0);
    cudaGetSymbolAddress((void**)&o1,   g_o1);
    cudaGetSymbolAddress((void**)&o2,   g_o2);
    cudaGetSymbolAddress((void**)&l0,   g_l0);
    cudaGetSymbolAddress((void**)&l1,   g_l1);
    cudaGetSymbolAddress((void**)&l2,   g_l2);

    float* qp = qkvp;
    float* kp = qkvp + (size_t)NTOK * C_;
    float* vp = qkvp + 2 * (size_t)NTOK * C_;

    cudaFuncSetAttribute(gemm_mma, cudaFuncAttributeMaxDynamicSharedMemorySize,
                         GEMM_SMEM);
    const size_t attn_smem = (size_t)ATTN_SMEM_FLOATS * sizeof(float);
    cudaFuncSetAttribute(attn_kernel,
                         cudaFuncAttributeMaxDynamicSharedMemorySize,
                         (int)attn_smem);

    // 0) conversions
    xsplit<<<8192, 256>>>(x, xs);
    wsplitT<<<dim3(32, 32), dim3(32, 8)>>>(q_w, 1024, 1024, wq);
    wsplitT<<<dim3(32, 32), dim3(32, 8)>>>(k_w, 1024, 1024, wk);
    wsplitT<<<dim3(32, 32), dim3(32, 8)>>>(v_w, 1024, 1024, wv);
    wsplitT<<<dim3(32, 32), dim3(32, 8)>>>(o_w, 1024, 1024, wo);
    rowsplit<<<1024, 256>>>(c_attn_w, 3072, 0,    wcr);
    rowsplit<<<1024, 256>>>(c_attn_w, 3072, 1024, wcr + (size_t)1024 * 2048);
    rowsplit<<<1024, 256>>>(c_attn_w, 3072, 2048, wcr + (size_t)2048 * 2048);
    biasfold3<<<3, 1024>>>(c_attn_b, q_w, k_w, v_w, q_b, k_b, v_b, bf);

    // 1) fused-weight prep: Wf_s = Wc_slice_s @ W_s  (transposed-split output)
    gemm_mma<<<dim3(8, 8), 256, GEMM_SMEM>>>(
        wcr,                       2048, 0, 1024, wq, 2048, 0, 1024,
        zero, wf,                         2048, 1024, 32, 3, 1.f);
    gemm_mma<<<dim3(8, 8), 256, GEMM_SMEM>>>(
        wcr + (size_t)1024 * 2048, 2048, 0, 1024, wk, 2048, 0, 1024,
        zero, wf + (size_t)1024 * 2048,   2048, 1024, 32, 3, 1.f);
    gemm_mma<<<dim3(8, 8), 256, GEMM_SMEM>>>(
        wcr + (size_t)2048 * 2048, 2048, 0, 1024, wv, 2048, 0, 1024,
        zero, wf + (size_t)2048 * 2048,   2048, 1024, 32, 3, 1.f);

    // 2) merged projection: q/k/v = x @ Wf + bf -> [s][B,H,T,D]; q scaled
    gemm_mma<<<dim3(24, 64), 256, GEMM_SMEM>>>(
        xs, 2048, 0, 1024, wf, 2048, 0, 1024, bf,
        qkvp, 0, 0, 32, 1, 0.125f);

    // 3) dilated attention branches (fp32)
    attn_kernel<<<dim3(4, 8, B_ * H_), 256, attn_smem>>>(qp, kp, vp, o0, l0,
                                                         512, 1, 4096);
    attn_kernel<<<dim3(4, 4, B_ * H_), 256, attn_smem>>>(qp, kp, vp, o1, l1,
                                                         1024, 2, 2048);
    attn_kernel<<<dim3(4, 2, B_ * H_), 256, attn_smem>>>(qp, kp, vp, o2, l2,
                                                         2048, 4, 1024);
    // 4) combine -> split bf16 y2
    combine_kernel<<<dim3(B_ * H_ * T_ / 128), 128>>>(o0, o1, o2, l0, l1, l2,
                                                      y2);
    // 5) out = y @ o_w + o_b  (fp32 to d_out)
    gemm_mma<<<dim3(8, 64), 256, GEMM_SMEM>>>(
        y2, 2048, 0, 1024, wo, 2048, 0, 1024, o_b,
        out, 1024, 0, 32, 0, 1.f);
}

// round 8
// speedup vs baseline: 2.4570x; 1.2259x over previous
#include <cuda_runtime.h>
#include <cuda_bf16.h>
#include <cstdint>

// Problem constants
#define B_   2
#define T_   4096
#define C_   1024
#define H_   16
#define D_   64
#define NTOK 8192   // B_*T_

// ---------------------------------------------------------------------------
// Scratch (static device globals; no runtime allocation allowed)
// ---------------------------------------------------------------------------
__device__ __nv_bfloat16 g_xs  [(size_t)NTOK * 2048];   // x split [hi|lo]
__device__ __nv_bfloat16 g_wq  [(size_t)1024 * 2048];   // Wq^T split
__device__ __nv_bfloat16 g_wk  [(size_t)1024 * 2048];
__device__ __nv_bfloat16 g_wv  [(size_t)1024 * 2048];
__device__ __nv_bfloat16 g_wo  [(size_t)1024 * 2048];
__device__ __nv_bfloat16 g_wcr [(size_t)3 * 1024 * 2048]; // Wc slices row-split
__device__ __nv_bfloat16 g_wf  [(size_t)3072 * 2048];   // fused W^T split [n,2k]
__device__ float g_bf[3072];                            // fused biases
__device__ float g_zero[1024];                          // zero bias (static 0)
// q/k/v as split bf16: [s][bh][t][128] rows = hi(64) | lo(64)
__device__ __nv_bfloat16 g_qkvb[(size_t)3 * 32 * T_ * 128];
__device__ float g_o0[(size_t)B_ * H_ * T_ * D_];
__device__ float g_o1[(size_t)B_ * H_ * (T_ / 2) * D_];
__device__ float g_o2[(size_t)B_ * H_ * (T_ / 4) * D_];
__device__ float g_l0[B_ * H_ * T_];
__device__ float g_l1[B_ * H_ * (T_ / 2)];
__device__ float g_l2[B_ * H_ * (T_ / 4)];
__device__ __nv_bfloat16 g_y2[(size_t)NTOK * 2048];     // combined split [hi|lo]

// ---------------------------------------------------------------------------
// PTX helpers (base sm_103 target: mma.sync / ldmatrix / cp.async only)
// ---------------------------------------------------------------------------
__device__ __forceinline__ uint32_t smem_u32(const void* p) {
    uint32_t a;
    asm("{ .reg .u64 t; cvta.to.shared.u64 t, %1; cvt.u32.u64 %0, t; }"
        : "=r"(a) : "l"(p));
    return a;
}
__device__ __forceinline__ void cp16(uint32_t dst, const void* src) {
    asm volatile("cp.async.cg.shared.global [%0], [%1], 16;\n"
                 :: "r"(dst), "l"(src));
}
__device__ __forceinline__ void ldm4(uint32_t* r, uint32_t a) {
    asm volatile("ldmatrix.sync.aligned.m8n8.x4.shared.b16 {%0,%1,%2,%3}, [%4];"
                 : "=r"(r[0]), "=r"(r[1]), "=r"(r[2]), "=r"(r[3]) : "r"(a));
}
__device__ __forceinline__ void mma16816(float* c, const uint32_t* a,
                                         const uint32_t* b) {
    asm volatile(
        "mma.sync.aligned.m16n8k16.row.col.f32.bf16.bf16.f32 "
        "{%0,%1,%2,%3}, {%4,%5,%6,%7}, {%8,%9}, {%0,%1,%2,%3};"
        : "+f"(c[0]), "+f"(c[1]), "+f"(c[2]), "+f"(c[3])
        : "r"(a[0]), "r"(a[1]), "r"(a[2]), "r"(a[3]), "r"(b[0]), "r"(b[1]));
}
// exp2 on the FMA pipe (degree-5 minimax on [0,1) + exponent-bit scale)
__device__ __forceinline__ float fexp2(float t) {
    t = fmaxf(t, -80.f);
    float fl = floorf(t);
    float f = t - fl;
    float p = 0.0013276471f;
    p = fmaf(p, f, 0.0096788383f);
    p = fmaf(p, f, 0.0555072548f);
    p = fmaf(p, f, 0.2402211502f);
    p = fmaf(p, f, 0.6931469902f);
    p = fmaf(p, f, 1.0f);
    int e = (int)fl;
    return p * __int_as_float((e + 127) << 23);
}

// ---------------------------------------------------------------------------
// Split-bf16 HMMA GEMM (unchanged core from R7).
// mode 0: fp32 store out[row*ldc + n]
// mode 1: split-bf16 qkv scatter to [s][bh][t][hi64|lo64]; s==0 scaled
// mode 3: transposed split store (fused-weight prep)
// ---------------------------------------------------------------------------
#define STAGEB 20480
#define GEMM_SMEM (4 * STAGEB)

__global__ __launch_bounds__(256) void gemm_mma(
    const __nv_bfloat16* __restrict__ A, int lda, int aHi, int aLo,
    const __nv_bfloat16* __restrict__ Bt, int ldb, int bHi, int bLo,
    const float* __restrict__ bias, void* __restrict__ outp,
    int ldc, int oLo, int NKC, int mode, float scale)
{
    extern __shared__ __align__(128) char smx[];
    const uint32_t su = smem_u32(smx);
    const int tid = threadIdx.x;
    const int warp = tid >> 5, lane = tid & 31;
    const int wm = warp >> 1, wn = warp & 1;
    const int m0 = blockIdx.y * 128, n0 = blockIdx.x * 128;
    const int NC = 3 * NKC;

    float acc[2][8][4];
#pragma unroll
    for (int i = 0; i < 2; i++)
#pragma unroll
        for (int j = 0; j < 8; j++)
#pragma unroll
            for (int q = 0; q < 4; q++) acc[i][j][q] = 0.f;

    auto loads = [&](int c, int s) {
        int ka, kb;
        if (c < NKC)            { ka = aHi + c * 32;            kb = bHi + c * 32; }
        else if (c < 2 * NKC)   { int k2 = c - NKC;     ka = aHi + k2 * 32; kb = bLo + k2 * 32; }
        else                    { int k2 = c - 2 * NKC; ka = aLo + k2 * 32; kb = bHi + k2 * 32; }
        uint32_t sa = su + (uint32_t)s * STAGEB;
        uint32_t sb = sa + 10240;
#pragma unroll
        for (int j = 0; j < 2; j++) {
            int f = tid + j * 256;
            int r = f >> 2, si = (f & 3) * 16;
            cp16(sa + r * 80 + si,
                 (const char*)(A + (size_t)(m0 + r) * lda + ka) + si);
            cp16(sb + r * 80 + si,
                 (const char*)(Bt + (size_t)(n0 + r) * ldb + kb) + si);
        }
        asm volatile("cp.async.commit_group;\n" ::: "memory");
    };

    loads(0, 0); loads(1, 1); loads(2, 2);

#pragma unroll 1
    for (int c = 0; c < NC; c++) {
        asm volatile("cp.async.wait_group 2;\n" ::: "memory");
        __syncthreads();
        if (c + 3 < NC) loads(c + 3, (c + 3) & 3);

        uint32_t sa = su + (uint32_t)(c & 3) * STAGEB;
        uint32_t sb = sa + 10240;
#pragma unroll
        for (int kk = 0; kk < 2; kk++) {
            uint32_t af[2][4];
#pragma unroll
            for (int mm = 0; mm < 2; mm++) {
                uint32_t addr = sa +
                    (uint32_t)(wm * 32 + mm * 16 + (lane & 15)) * 80 +
                    ((lane >> 4) << 4) + kk * 32;
                ldm4(af[mm], addr);
            }
            uint32_t bf[4][4];
#pragma unroll
            for (int nb = 0; nb < 4; nb++) {
                int rown = wn * 64 + nb * 16 + ((lane >> 4) & 1) * 8 + (lane & 7);
                uint32_t addr = sb + (uint32_t)rown * 80 +
                    (((lane >> 3) & 1) << 4) + kk * 32;
                ldm4(bf[nb], addr);
            }
#pragma unroll
            for (int mm = 0; mm < 2; mm++)
#pragma unroll
                for (int nn = 0; nn < 8; nn++)
                    mma16816(acc[mm][nn], af[mm], &bf[nn >> 1][(nn & 1) * 2]);
        }
    }

    const int r0 = m0 + wm * 32 + (lane >> 2);
    const int c0b = n0 + wn * 64 + (lane & 3) * 2;
#pragma unroll
    for (int mm = 0; mm < 2; mm++)
#pragma unroll
        for (int nn = 0; nn < 8; nn++) {
            float* cc = acc[mm][nn];
            int col = c0b + nn * 8;
#pragma unroll
            for (int hf = 0; hf < 2; hf++) {
                int row = r0 + mm * 16 + hf * 8;
                float v0 = cc[hf * 2 + 0] + bias[col];
                float v1 = cc[hf * 2 + 1] + bias[col + 1];
                if (mode == 0) {
                    float2 o; o.x = v0; o.y = v1;
                    *(float2*)((float*)outp + (size_t)row * ldc + col) = o;
                } else if (mode == 1) {
                    int s = col >> 10;
                    int c1 = col & 1023;
                    int h = c1 >> 6, d = c1 & 63;
                    float sc = (s == 0) ? scale : 1.f;
                    v0 *= sc; v1 *= sc;
                    int bI = row >> 12, t = row & 4095;
                    __nv_bfloat16* ob = (__nv_bfloat16*)outp;
                    size_t rb = ((size_t)(s * 32 + bI * 16 + h) * T_ + t) * 128;
                    __nv_bfloat162 hv, lv;
                    hv.x = __float2bfloat16(v0);
                    hv.y = __float2bfloat16(v1);
                    lv.x = __float2bfloat16(v0 - __bfloat162float(hv.x));
                    lv.y = __float2bfloat16(v1 - __bfloat162float(hv.y));
                    *(__nv_bfloat162*)&ob[rb + d] = hv;
                    *(__nv_bfloat162*)&ob[rb + 64 + d] = lv;
                } else {   // mode 3
                    __nv_bfloat16* ob = (__nv_bfloat16*)outp;
                    __nv_bfloat16 h0 = __float2bfloat16(v0);
                    ob[(size_t)col * ldc + row] = h0;
                    ob[(size_t)col * ldc + oLo + row] =
                        __float2bfloat16(v0 - __bfloat162float(h0));
                    __nv_bfloat16 h1 = __float2bfloat16(v1);
                    ob[(size_t)(col + 1) * ldc + row] = h1;
                    ob[(size_t)(col + 1) * ldc + oLo + row] =
                        __float2bfloat16(v1 - __bfloat162float(h1));
                }
            }
        }
}

// ---------------------------------------------------------------------------
// Conversions (unchanged from R7)
// ---------------------------------------------------------------------------
__global__ __launch_bounds__(256) void wsplitT(
    const float* __restrict__ W, int K, int N, __nv_bfloat16* __restrict__ Wt)
{
    __shared__ float tile[32][33];
    int n0 = blockIdx.x * 32, k0 = blockIdx.y * 32;
    int tx = threadIdx.x, ty = threadIdx.y;
#pragma unroll
    for (int i = 0; i < 32; i += 8)
        tile[ty + i][tx] = W[(size_t)(k0 + ty + i) * N + n0 + tx];
    __syncthreads();
#pragma unroll
    for (int i = 0; i < 32; i += 8) {
        int n = n0 + ty + i, k = k0 + tx;
        float v = tile[tx][ty + i];
        __nv_bfloat16 h = __float2bfloat16(v);
        Wt[(size_t)n * 2 * K + k] = h;
        Wt[(size_t)n * 2 * K + K + k] = __float2bfloat16(v - __bfloat162float(h));
    }
}

__global__ __launch_bounds__(256) void rowsplit(
    const float* __restrict__ W, int ldw, int colOff,
    __nv_bfloat16* __restrict__ out)
{
    int i = blockIdx.x;
    int c = threadIdx.x * 4;
    float4 v = *(const float4*)&W[(size_t)i * ldw + colOff + c];
    __nv_bfloat162 h0, h1, l0, l1;
    h0.x = __float2bfloat16(v.x); h0.y = __float2bfloat16(v.y);
    h1.x = __float2bfloat16(v.z); h1.y = __float2bfloat16(v.w);
    l0.x = __float2bfloat16(v.x - __bfloat162float(h0.x));
    l0.y = __float2bfloat16(v.y - __bfloat162float(h0.y));
    l1.x = __float2bfloat16(v.z - __bfloat162float(h1.x));
    l1.y = __float2bfloat16(v.w - __bfloat162float(h1.y));
    __nv_bfloat16* o = out + (size_t)i * 2048;
    *(__nv_bfloat162*)&o[c] = h0;
    *(__nv_bfloat162*)&o[c + 2] = h1;
    *(__nv_bfloat162*)&o[1024 + c] = l0;
    *(__nv_bfloat162*)&o[1024 + c + 2] = l1;
}

__global__ __launch_bounds__(256) void xsplit(
    const float* __restrict__ x, __nv_bfloat16* __restrict__ xs)
{
    size_t i = (size_t)blockIdx.x * 256 + threadIdx.x;
    size_t r = i >> 8;
    int c = (int)(i & 255) * 4;
    float4 v = *(const float4*)&x[r * 1024 + c];
    __nv_bfloat162 h0, h1, l0, l1;
    h0.x = __float2bfloat16(v.x); h0.y = __float2bfloat16(v.y);
    h1.x = __float2bfloat16(v.z); h1.y = __float2bfloat16(v.w);
    l0.x = __float2bfloat16(v.x - __bfloat162float(h0.x));
    l0.y = __float2bfloat16(v.y - __bfloat162float(h0.y));
    l1.x = __float2bfloat16(v.z - __bfloat162float(h1.x));
    l1.y = __float2bfloat16(v.w - __bfloat162float(h1.y));
    *(__nv_bfloat162*)&xs[r * 2048 + c] = h0;
    *(__nv_bfloat162*)&xs[r * 2048 + c + 2] = h1;
    *(__nv_bfloat162*)&xs[r * 2048 + 1024 + c] = l0;
    *(__nv_bfloat162*)&xs[r * 2048 + 1024 + c + 2] = l1;
}

__global__ __launch_bounds__(1024) void biasfold3(
    const float* __restrict__ bc,
    const float* __restrict__ Wq, const float* __restrict__ Wk,
    const float* __restrict__ Wv,
    const float* __restrict__ bq, const float* __restrict__ bk,
    const float* __restrict__ bv,
    float* __restrict__ out)
{
    int s = blockIdx.x;
    int n = threadIdx.x;
    const float* W  = (s == 0) ? Wq : (s == 1) ? Wk : Wv;
    const float* b2 = (s == 0) ? bq : (s == 1) ? bk : bv;
    const float* bs = bc + s * 1024;
    float a0 = 0.f, a1 = 0.f, a2 = 0.f, a3 = 0.f;
#pragma unroll 1
    for (int m = 0; m < 1024; m += 16) {
#pragma unroll
        for (int j = 0; j < 16; j++) {
            float w = W[(size_t)(m + j) * 1024 + n];
            float bb = bs[m + j];
            if ((j & 3) == 0) a0 = fmaf(bb, w, a0);
            else if ((j & 3) == 1) a1 = fmaf(bb, w, a1);
            else if ((j & 3) == 2) a2 = fmaf(bb, w, a2);
            else a3 = fmaf(bb, w, a3);
        }
    }
    out[s * 1024 + n] = a0 + a1 + a2 + a3 + b2[n];
}

// ---------------------------------------------------------------------------
// HMMA dilated attention. CTA = 128 q-rows x 128 keys, 8 warps x 16 rows.
// q/k/v: split bf16 [s][bh][t][hi64|lo64]. 3-term split QK and PV.
// exp on FMA pipe (fexp2). V transposed to d-major in smem at load.
// ---------------------------------------------------------------------------
#define AP 272
#define ATTN2_SMEM (3 * 128 * AP)   // 104448 B

__global__ void __launch_bounds__(256, 1) attn2(
    const __nv_bfloat16* __restrict__ qkvb,
    float* __restrict__ obr, float* __restrict__ lbr,
    int w, int r, int Tr)
{
    extern __shared__ __align__(128) char sm2[];
    const uint32_t Qs = smem_u32(sm2);
    const uint32_t Ks = Qs + 128 * AP;
    const uint32_t Vt = Ks + 128 * AP;

    const int tid = threadIdx.x;
    const int warp = tid >> 5, lane = tid & 31;
    const int m0 = blockIdx.x * 128;
    const int seg = blockIdx.y;
    const int bh = blockIdx.z;
    const int h = bh & 15;
    const int off = h & (r - 1);
    const int segbase = seg * w + off;
    const __nv_bfloat16* qb = qkvb;
    const __nv_bfloat16* kb = qkvb + (size_t)32 * T_ * 128;
    const __nv_bfloat16* vb = qkvb + (size_t)64 * T_ * 128;
    const size_t bhbase = (size_t)bh * T_;

    // Q tile (once)
#pragma unroll
    for (int j = 0; j < 8; j++) {
        int f = tid + j * 256;
        int row = f >> 4, si = f & 15;
        const __nv_bfloat16* g =
            qb + (bhbase + segbase + (size_t)(m0 + row) * r) * 128 + si * 8;
        cp16(Qs + row * AP + si * 16, g);
    }
    asm volatile("cp.async.commit_group;\n" ::: "memory");

    float S[16][4];
    float O[8][4];
#pragma unroll
    for (int i = 0; i < 8; i++)
#pragma unroll
        for (int j2 = 0; j2 < 4; j2++) O[i][j2] = 0.f;
    float ml[2] = {-1e30f, -1e30f};
    float ll[2] = {0.f, 0.f};

    const int ntile = (m0 >> 7) + 1;
#pragma unroll 1
    for (int nt = 0; nt < ntile; nt++) {
        const int n0 = nt * 128;
        if (nt > 0) __syncthreads();   // previous tile compute done

        // K tile (gathered rows, cp.async)
#pragma unroll
        for (int j = 0; j < 8; j++) {
            int f = tid + j * 256;
            int row = f >> 4, si = f & 15;
            const __nv_bfloat16* g =
                kb + (bhbase + segbase + (size_t)(n0 + row) * r) * 128 + si * 8;
            cp16(Ks + row * AP + si * 16, g);
        }
        asm volatile("cp.async.commit_group;\n" ::: "memory");

        // V tile: load rows, write transposed (d-major) to smem
#pragma unroll
        for (int j = 0; j < 8; j++) {
            int f = tid + j * 256;
            int key = f & 127, si = f >> 7;
            const uint4 vv = *(const uint4*)(
                vb + (bhbase + segbase + (size_t)(n0 + key) * r) * 128 + si * 8);
            const uint16_t* pv = (const uint16_t*)&vv;
#pragma unroll
            for (int e = 0; e < 8; e++)
                asm volatile("st.shared.u16 [%0], %1;" ::
                             "r"(Vt + (si * 8 + e) * AP + key * 2), "h"(pv[e]));
        }
        asm volatile("cp.async.wait_group 0;\n" ::: "memory");
        __syncthreads();

        // ---- S = Q K^T, 3-term split ----
#pragma unroll
        for (int t = 0; t < 16; t++)
#pragma unroll
            for (int j2 = 0; j2 < 4; j2++) S[t][j2] = 0.f;

#pragma unroll
        for (int kk = 0; kk < 4; kk++) {
            uint32_t qh[4], qlo[4];
            uint32_t abase = Qs + (uint32_t)(warp * 16 + (lane & 15)) * AP +
                             ((lane >> 4) << 4) + kk * 32;
            ldm4(qh, abase);
            ldm4(qlo, abase + 128);
#pragma unroll
            for (int hf = 0; hf < 2; hf++) {
                uint32_t kh[4][4], kl2[4][4];
#pragma unroll
                for (int nb = 0; nb < 4; nb++) {
                    int rowk = hf * 64 + nb * 16 + ((lane >> 4) & 1) * 8 + (lane & 7);
                    uint32_t kaddr = Ks + (uint32_t)rowk * AP +
                                     (((lane >> 3) & 1) << 4) + kk * 32;
                    ldm4(kh[nb], kaddr);
                    ldm4(kl2[nb], kaddr + 128);
                }
#pragma unroll
                for (int nn = 0; nn < 8; nn++) {
                    int t = hf * 8 + nn;
                    const uint32_t* bh2 = &kh[nn >> 1][(nn & 1) * 2];
                    const uint32_t* bl2 = &kl2[nn >> 1][(nn & 1) * 2];
                    mma16816(S[t], qh, bh2);
                    mma16816(S[t], qlo, bh2);
                    mma16816(S[t], qh, bl2);
                }
            }
        }

        // Causal mask on the diagonal tile
        if (n0 == m0) {
#pragma unroll
            for (int t = 0; t < 16; t++) {
                int colb = n0 + t * 8 + (lane & 3) * 2;
#pragma unroll
                for (int j2 = 0; j2 < 4; j2++) {
                    int rowg = m0 + warp * 16 + (lane >> 2) + (j2 >> 1) * 8;
                    if (colb + (j2 & 1) > rowg) S[t][j2] = -1e30f;
                }
            }
        }

        // Online softmax (warp-local rows; quad shuffle reduce)
#pragma unroll
        for (int rr = 0; rr < 2; rr++) {
            float vmax = -1e30f;
#pragma unroll
            for (int t = 0; t < 16; t++) {
                vmax = fmaxf(vmax, S[t][rr * 2 + 0]);
                vmax = fmaxf(vmax, S[t][rr * 2 + 1]);
            }
            vmax = fmaxf(vmax, __shfl_xor_sync(0xffffffffu, vmax, 1));
            vmax = fmaxf(vmax, __shfl_xor_sync(0xffffffffu, vmax, 2));
            float mn = fmaxf(ml[rr], vmax);
            float alpha = __expf(ml[rr] - mn);
            ml[rr] = mn;
            float rs = 0.f;
#pragma unroll
            for (int t = 0; t < 16; t++) {
                float e0 = fexp2((S[t][rr * 2 + 0] - mn) * 1.44269504f);
                float e1 = fexp2((S[t][rr * 2 + 1] - mn) * 1.44269504f);
                S[t][rr * 2 + 0] = e0;
                S[t][rr * 2 + 1] = e1;
                rs += e0 + e1;
            }
            rs += __shfl_xor_sync(0xffffffffu, rs, 1);
            rs += __shfl_xor_sync(0xffffffffu, rs, 2);
            ll[rr] = ll[rr] * alpha + rs;
#pragma unroll
            for (int nn = 0; nn < 8; nn++) {
                O[nn][rr * 2 + 0] *= alpha;
                O[nn][rr * 2 + 1] *= alpha;
            }
        }

        // ---- O += P V, 3-term split; P fed straight from S registers ----
#pragma unroll
        for (int ks = 0; ks < 8; ks++) {
            uint32_t ph[4], pl[4];
#pragma unroll
            for (int q2 = 0; q2 < 4; q2++) {
                int t = ks * 2 + (q2 >> 1);
                float a = S[t][(q2 & 1) * 2 + 0];
                float b = S[t][(q2 & 1) * 2 + 1];
                __nv_bfloat162 hv;
                hv.x = __float2bfloat16(a);
                hv.y = __float2bfloat16(b);
                ph[q2] = *(uint32_t*)&hv;
                __nv_bfloat162 lv;
                lv.x = __float2bfloat16(a - __bfloat162float(hv.x));
                lv.y = __float2bfloat16(b - __bfloat162float(hv.y));
                pl[q2] = *(uint32_t*)&lv;
            }
            uint32_t vh[4][4], vl2[4][4];
#pragma unroll
            for (int nb = 0; nb < 4; nb++) {
                int rowd = nb * 16 + ((lane >> 4) & 1) * 8 + (lane & 7);
                uint32_t vaddr = Vt + (uint32_t)rowd * AP +
                                 (((lane >> 3) & 1) << 4) + ks * 32;
                ldm4(vh[nb], vaddr);
                ldm4(vl2[nb], vaddr + 64 * AP);
            }
#pragma unroll
            for (int nn = 0; nn < 8; nn++) {
                const uint32_t* bh2 = &vh[nn >> 1][(nn & 1) * 2];
                const uint32_t* bl2 = &vl2[nn >> 1][(nn & 1) * 2];
                mma16816(O[nn], ph, bh2);
                mma16816(O[nn], pl, bh2);
                mma16816(O[nn], ph, bl2);
            }
        }
    }

    // Epilogue: normalize, write compact branch output + lse
#pragma unroll
    for (int rr = 0; rr < 2; rr++) {
        float inv = 1.f / ll[rr];
        size_t orow = (size_t)bh * Tr + seg * 512 + m0 + warp * 16 +
                      (lane >> 2) + rr * 8;
#pragma unroll
        for (int nn = 0; nn < 8; nn++) {
            float2 o2;
            o2.x = O[nn][rr * 2 + 0] * inv;
            o2.y = O[nn][rr * 2 + 1] * inv;
            *(float2*)&obr[orow * D_ + nn * 8 + (lane & 3) * 2] = o2;
        }
        if ((lane & 3) == 0) lbr[orow] = ml[rr] + logf(ll[rr]);
    }
}

// ---------------------------------------------------------------------------
// Combine branches with LSE weights; emit split bf16 y2 [8192, 2048]
// ---------------------------------------------------------------------------
__global__ __launch_bounds__(128) void combine_kernel(
    const float* __restrict__ o0, const float* __restrict__ o1,
    const float* __restrict__ o2,
    const float* __restrict__ l0, const float* __restrict__ l1,
    const float* __restrict__ l2,
    __nv_bfloat16* __restrict__ y2)
{
    int rowid = blockIdx.x * 128 + threadIdx.x;
    int bh = rowid >> 12;
    int t = rowid & 4095;
    int h = bh & (H_ - 1);
    int b = bh >> 4;

    float L0 = l0[(size_t)bh * 4096 + t];
    bool c1 = ((t & 1) == (h & 1));
    bool c2 = ((t & 3) == (h & 3));
    size_t i1 = (size_t)bh * 2048 + ((size_t)(t >> 10) << 9) + ((t & 1023) >> 1);
    size_t i2 = (size_t)bh * 1024 + ((size_t)(t >> 11) << 9) + ((t & 2047) >> 2);
    float L1 = c1 ? l1[i1] : -1e30f;
    float L2 = c2 ? l2[i2] : -1e30f;
    float m = fmaxf(L0, fmaxf(L1, L2));
    float w0 = __expf(L0 - m);
    float w1 = c1 ? __expf(L1 - m) : 0.f;
    float w2 = c2 ? __expf(L2 - m) : 0.f;
    float inv = 1.f / (w0 + w1 + w2);
    w0 *= inv; w1 *= inv; w2 *= inv;

    const float* p0 = o0 + ((size_t)bh * 4096 + t) * D_;
    const float* p1 = o1 + i1 * D_;
    const float* p2 = o2 + i2 * D_;
    size_t ybase = (size_t)(b * 4096 + t) * 2048 + h * D_;

#pragma unroll
    for (int d = 0; d < 64; d += 4) {
        float4 a0 = *(const float4*)&p0[d];
        float4 res = make_float4(w0 * a0.x, w0 * a0.y, w0 * a0.z, w0 * a0.w);
        if (c1) {
            float4 a1 = *(const float4*)&p1[d];
            res.x += w1 * a1.x; res.y += w1 * a1.y;
            res.z += w1 * a1.z; res.w += w1 * a1.w;
        }
        if (c2) {
            float4 a2 = *(const float4*)&p2[d];
            res.x += w2 * a2.x; res.y += w2 * a2.y;
            res.z += w2 * a2.z; res.w += w2 * a2.w;
        }
        __nv_bfloat162 h0, h1, lo0, lo1;
        h0.x = __float2bfloat16(res.x); h0.y = __float2bfloat16(res.y);
        h1.x = __float2bfloat16(res.z); h1.y = __float2bfloat16(res.w);
        lo0.x = __float2bfloat16(res.x - __bfloat162float(h0.x));
        lo0.y = __float2bfloat16(res.y - __bfloat162float(h0.y));
        lo1.x = __float2bfloat16(res.z - __bfloat162float(h1.x));
        lo1.y = __float2bfloat16(res.w - __bfloat162float(h1.y));
        *(__nv_bfloat162*)&y2[ybase + d] = h0;
        *(__nv_bfloat162*)&y2[ybase + d + 2] = h1;
        *(__nv_bfloat162*)&y2[ybase + 1024 + d] = lo0;
        *(__nv_bfloat162*)&y2[ybase + 1024 + d + 2] = lo1;
    }
}

// ---------------------------------------------------------------------------
// Launch
// ---------------------------------------------------------------------------
extern "C" void kernel_launch(void* const* d_in, const int* in_sizes, int n_in,
                              void* d_out, int out_size)
{
    (void)in_sizes; (void)n_in; (void)out_size;
    const float* x        = (const float*)d_in[0];
    const float* c_attn_w = (const float*)d_in[1];
    const float* c_attn_b = (const float*)d_in[2];
    const float* q_w      = (const float*)d_in[3];
    const float* q_b      = (const float*)d_in[4];
    const float* k_w      = (const float*)d_in[5];
    const float* k_b      = (const float*)d_in[6];
    const float* v_w      = (const float*)d_in[7];
    const float* v_b      = (const float*)d_in[8];
    const float* o_w      = (const float*)d_in[9];
    const float* o_b      = (const float*)d_in[10];
    float* out = (float*)d_out;

    __nv_bfloat16 *xs, *wq, *wk, *wv, *wo, *wcr, *wf, *y2, *qkvb;
    float *bf, *zero, *o0, *o1, *o2, *l0, *l1, *l2;
    cudaGetSymbolAddress((void**)&xs,   g_xs);
    cudaGetSymbolAddress((void**)&wq,   g_wq);
    cudaGetSymbolAddress((void**)&wk,   g_wk);
    cudaGetSymbolAddress((void**)&wv,   g_wv);
    cudaGetSymbolAddress((void**)&wo,   g_wo);
    cudaGetSymbolAddress((void**)&wcr,  g_wcr);
    cudaGetSymbolAddress((void**)&wf,   g_wf);
    cudaGetSymbolAddress((void**)&bf,   g_bf);
    cudaGetSymbolAddress((void**)&zero, g_zero);
    cudaGetSymbolAddress((void**)&qkvb, g_qkvb);
    cudaGetSymbolAddress((void**)&y2,   g_y2);
    cudaGetSymbolAddress((void**)&o0,   g_o0);
    cudaGetSymbolAddress((void**)&o1,   g_o1);
    cudaGetSymbolAddress((void**)&o2,   g_o2);
    cudaGetSymbolAddress((void**)&l0,   g_l0);
    cudaGetSymbolAddress((void**)&l1,   g_l1);
    cudaGetSymbolAddress((void**)&l2,   g_l2);

    cudaFuncSetAttribute(gemm_mma, cudaFuncAttributeMaxDynamicSharedMemorySize,
                         GEMM_SMEM);
    cudaFuncSetAttribute(attn2, cudaFuncAttributeMaxDynamicSharedMemorySize,
                         ATTN2_SMEM);

    // 0) conversions
    xsplit<<<8192, 256>>>(x, xs);
    wsplitT<<<dim3(32, 32), dim3(32, 8)>>>(q_w, 1024, 1024, wq);
    wsplitT<<<dim3(32, 32), dim3(32, 8)>>>(k_w, 1024, 1024, wk);
    wsplitT<<<dim3(32, 32), dim3(32, 8)>>>(v_w, 1024, 1024, wv);
    wsplitT<<<dim3(32, 32), dim3(32, 8)>>>(o_w, 1024, 1024, wo);
    rowsplit<<<1024, 256>>>(c_attn_w, 3072, 0,    wcr);
    rowsplit<<<1024, 256>>>(c_attn_w, 3072, 1024, wcr + (size_t)1024 * 2048);
    rowsplit<<<1024, 256>>>(c_attn_w, 3072, 2048, wcr + (size_t)2048 * 2048);
    biasfold3<<<3, 1024>>>(c_attn_b, q_w, k_w, v_w, q_b, k_b, v_b, bf);

    // 1) fused-weight prep: Wf_s = Wc_slice_s @ W_s (transposed-split out)
    gemm_mma<<<dim3(8, 8), 256, GEMM_SMEM>>>(
        wcr,                       2048, 0, 1024, wq, 2048, 0, 1024,
        zero, wf,                         2048, 1024, 32, 3, 1.f);
    gemm_mma<<<dim3(8, 8), 256, GEMM_SMEM>>>(
        wcr + (size_t)1024 * 2048, 2048, 0, 1024, wk, 2048, 0, 1024,
        zero, wf + (size_t)1024 * 2048,   2048, 1024, 32, 3, 1.f);
    gemm_mma<<<dim3(8, 8), 256, GEMM_SMEM>>>(
        wcr + (size_t)2048 * 2048, 2048, 0, 1024, wv, 2048, 0, 1024,
        zero, wf + (size_t)2048 * 2048,   2048, 1024, 32, 3, 1.f);

    // 2) merged projection: q/k/v = x @ Wf + bf -> split bf16 [s][bh][t][hi|lo]
    gemm_mma<<<dim3(24, 64), 256, GEMM_SMEM>>>(
        xs, 2048, 0, 1024, wf, 2048, 0, 1024, bf,
        qkvb, 0, 0, 32, 1, 0.125f);

    // 3) HMMA dilated attention branches
    attn2<<<dim3(4, 8, 32), 256, ATTN2_SMEM>>>(qkvb, o0, l0, 512, 1, 4096);
    attn2<<<dim3(4, 4, 32), 256, ATTN2_SMEM>>>(qkvb, o1, l1, 1024, 2, 2048);
    attn2<<<dim3(4, 2, 32), 256, ATTN2_SMEM>>>(qkvb, o2, l2, 2048, 4, 1024);

    // 4) combine -> split bf16 y2
    combine_kernel<<<dim3(B_ * H_ * T_ / 128), 128>>>(o0, o1, o2, l0, l1, l2,
                                                      y2);
    // 5) out = y @ o_w + o_b
    gemm_mma<<<dim3(8, 64), 256, GEMM_SMEM>>>(
        y2, 2048, 0, 1024, wo, 2048, 0, 1024, o_b,
        out, 1024, 0, 32, 0, 1.f);
}

// round 12
// speedup vs baseline: 2.6903x; 1.0950x over previous
#include <cuda_runtime.h>
#include <cuda_bf16.h>
#include <cstdint>

// Problem constants
#define B_   2
#define T_   4096
#define C_   1024
#define H_   16
#define D_   64
#define NTOK 8192   // B_*T_

// ---------------------------------------------------------------------------
// Scratch (static device globals; no runtime allocation allowed)
// ---------------------------------------------------------------------------
__device__ __nv_bfloat16 g_xs  [(size_t)NTOK * 2048];   // x split [hi|lo]
__device__ __nv_bfloat16 g_wqkv[(size_t)3 * 1024 * 2048]; // Wq/Wk/Wv^T split
__device__ __nv_bfloat16 g_wo  [(size_t)1024 * 2048];
__device__ __nv_bfloat16 g_wcr [(size_t)3 * 1024 * 2048]; // Wc slices row-split
__device__ __nv_bfloat16 g_wf  [(size_t)3072 * 2048];   // fused W^T split [n,2k]
__device__ float g_bf[3072];                            // fused biases
__device__ float g_zero[1024];                          // zero bias (static 0)
// q/k/v as split bf16: [s][bh][t][128] rows = hi(64) | lo(64)
__device__ __nv_bfloat16 g_qkvb[(size_t)3 * 32 * T_ * 128];
__device__ float g_o0[(size_t)B_ * H_ * T_ * D_];
__device__ float g_o1[(size_t)B_ * H_ * (T_ / 2) * D_];
__device__ float g_o2[(size_t)B_ * H_ * (T_ / 4) * D_];
__device__ float g_l0[B_ * H_ * T_];
__device__ float g_l1[B_ * H_ * (T_ / 2)];
__device__ float g_l2[B_ * H_ * (T_ / 4)];
__device__ __nv_bfloat16 g_y2[(size_t)NTOK * 2048];     // combined split [hi|lo]

// ---------------------------------------------------------------------------
// PTX helpers (base sm_103 target: mma.sync / ldmatrix / cp.async only)
// ---------------------------------------------------------------------------
__device__ __forceinline__ uint32_t smem_u32(const void* p) {
    uint32_t a;
    asm("{ .reg .u64 t; cvta.to.shared.u64 t, %1; cvt.u32.u64 %0, t; }"
        : "=r"(a) : "l"(p));
    return a;
}
__device__ __forceinline__ void cp16(uint32_t dst, const void* src) {
    asm volatile("cp.async.cg.shared.global [%0], [%1], 16;\n"
                 :: "r"(dst), "l"(src));
}
__device__ __forceinline__ void ldm4(uint32_t* r, uint32_t a) {
    asm volatile("ldmatrix.sync.aligned.m8n8.x4.shared.b16 {%0,%1,%2,%3}, [%4];"
                 : "=r"(r[0]), "=r"(r[1]), "=r"(r[2]), "=r"(r[3]) : "r"(a));
}
__device__ __forceinline__ void mma16816(float* c, const uint32_t* a,
                                         const uint32_t* b) {
    asm volatile(
        "mma.sync.aligned.m16n8k16.row.col.f32.bf16.bf16.f32 "
        "{%0,%1,%2,%3}, {%4,%5,%6,%7}, {%8,%9}, {%0,%1,%2,%3};"
        : "+f"(c[0]), "+f"(c[1]), "+f"(c[2]), "+f"(c[3])
        : "r"(a[0]), "r"(a[1]), "r"(a[2]), "r"(a[3]), "r"(b[0]), "r"(b[1]));
}
// exp2 on the FMA pipe (degree-5 minimax on [0,1) + exponent-bit scale)
__device__ __forceinline__ float fexp2(float t) {
    t = fmaxf(t, -80.f);
    float fl = floorf(t);
    float f = t - fl;
    float p = 0.0013276471f;
    p = fmaf(p, f, 0.0096788383f);
    p = fmaf(p, f, 0.0555072548f);
    p = fmaf(p, f, 0.2402211502f);
    p = fmaf(p, f, 0.6931469902f);
    p = fmaf(p, f, 1.0f);
    int e = (int)fl;
    return p * __int_as_float((e + 127) << 23);
}

// ---------------------------------------------------------------------------
// Split-bf16 HMMA GEMM. grid.z batching via byte strides zbA/zbB/zbO.
// mode 0: fp32 store out[row*ldc + n]
// mode 1: split-bf16 qkv scatter to [s][bh][t][hi64|lo64]; s==0 scaled
// mode 3: transposed split store (fused-weight prep)
// ---------------------------------------------------------------------------
#define STAGEB 20480
#define GEMM_SMEM (4 * STAGEB)

__global__ __launch_bounds__(256) void gemm_mma(
    const __nv_bfloat16* __restrict__ A0, int lda, int aHi, int aLo,
    const __nv_bfloat16* __restrict__ Bt0, int ldb, int bHi, int bLo,
    const float* __restrict__ bias, void* __restrict__ outp0,
    int ldc, int oLo, int NKC, int mode, float scale,
    size_t zbA, size_t zbB, size_t zbO)
{
    const __nv_bfloat16* A =
        (const __nv_bfloat16*)((const char*)A0 + (size_t)blockIdx.z * zbA);
    const __nv_bfloat16* Bt =
        (const __nv_bfloat16*)((const char*)Bt0 + (size_t)blockIdx.z * zbB);
    void* outp = (char*)outp0 + (size_t)blockIdx.z * zbO;

    extern __shared__ __align__(128) char smx[];
    const uint32_t su = smem_u32(smx);
    const int tid = threadIdx.x;
    const int warp = tid >> 5, lane = tid & 31;
    const int wm = warp >> 1, wn = warp & 1;
    const int m0 = blockIdx.y * 128, n0 = blockIdx.x * 128;
    const int NC = 3 * NKC;

    float acc[2][8][4];
#pragma unroll
    for (int i = 0; i < 2; i++)
#pragma unroll
        for (int j = 0; j < 8; j++)
#pragma unroll
            for (int q = 0; q < 4; q++) acc[i][j][q] = 0.f;

    auto loads = [&](int c, int s) {
        int ka, kb;
        if (c < NKC)            { ka = aHi + c * 32;            kb = bHi + c * 32; }
        else if (c < 2 * NKC)   { int k2 = c - NKC;     ka = aHi + k2 * 32; kb = bLo + k2 * 32; }
        else                    { int k2 = c - 2 * NKC; ka = aLo + k2 * 32; kb = bHi + k2 * 32; }
        uint32_t sa = su + (uint32_t)s * STAGEB;
        uint32_t sb = sa + 10240;
#pragma unroll
        for (int j = 0; j < 2; j++) {
            int f = tid + j * 256;
            int r = f >> 2, si = (f & 3) * 16;
            cp16(sa + r * 80 + si,
                 (const char*)(A + (size_t)(m0 + r) * lda + ka) + si);
            cp16(sb + r * 80 + si,
                 (const char*)(Bt + (size_t)(n0 + r) * ldb + kb) + si);
        }
        asm volatile("cp.async.commit_group;\n" ::: "memory");
    };

    loads(0, 0); loads(1, 1); loads(2, 2);

#pragma unroll 1
    for (int c = 0; c < NC; c++) {
        asm volatile("cp.async.wait_group 2;\n" ::: "memory");
        __syncthreads();
        if (c + 3 < NC) loads(c + 3, (c + 3) & 3);

        uint32_t sa = su + (uint32_t)(c & 3) * STAGEB;
        uint32_t sb = sa + 10240;
#pragma unroll
        for (int kk = 0; kk < 2; kk++) {
            uint32_t af[2][4];
#pragma unroll
            for (int mm = 0; mm < 2; mm++) {
                uint32_t addr = sa +
                    (uint32_t)(wm * 32 + mm * 16 + (lane & 15)) * 80 +
                    ((lane >> 4) << 4) + kk * 32;
                ldm4(af[mm], addr);
            }
            uint32_t bf[4][4];
#pragma unroll
            for (int nb = 0; nb < 4; nb++) {
                int rown = wn * 64 + nb * 16 + ((lane >> 4) & 1) * 8 + (lane & 7);
                uint32_t addr = sb + (uint32_t)rown * 80 +
                    (((lane >> 3) & 1) << 4) + kk * 32;
                ldm4(bf[nb], addr);
            }
#pragma unroll
            for (int mm = 0; mm < 2; mm++)
#pragma unroll
                for (int nn = 0; nn < 8; nn++)
                    mma16816(acc[mm][nn], af[mm], &bf[nn >> 1][(nn & 1) * 2]);
        }
    }

    const int r0 = m0 + wm * 32 + (lane >> 2);
    const int c0b = n0 + wn * 64 + (lane & 3) * 2;
#pragma unroll
    for (int mm = 0; mm < 2; mm++)
#pragma unroll
        for (int nn = 0; nn < 8; nn++) {
            float* cc = acc[mm][nn];
            int col = c0b + nn * 8;
#pragma unroll
            for (int hf = 0; hf < 2; hf++) {
                int row = r0 + mm * 16 + hf * 8;
                float v0 = cc[hf * 2 + 0] + bias[col];
                float v1 = cc[hf * 2 + 1] + bias[col + 1];
                if (mode == 0) {
                    float2 o; o.x = v0; o.y = v1;
                    *(float2*)((float*)outp + (size_t)row * ldc + col) = o;
                } else if (mode == 1) {
                    int s = col >> 10;
                    int c1 = col & 1023;
                    int h = c1 >> 6, d = c1 & 63;
                    float sc = (s == 0) ? scale : 1.f;
                    v0 *= sc; v1 *= sc;
                    int bI = row >> 12, t = row & 4095;
                    __nv_bfloat16* ob = (__nv_bfloat16*)outp;
                    size_t rb = ((size_t)(s * 32 + bI * 16 + h) * T_ + t) * 128;
                    __nv_bfloat162 hv, lv;
                    hv.x = __float2bfloat16(v0);
                    hv.y = __float2bfloat16(v1);
                    lv.x = __float2bfloat16(v0 - __bfloat162float(hv.x));
                    lv.y = __float2bfloat16(v1 - __bfloat162float(hv.y));
                    *(__nv_bfloat162*)&ob[rb + d] = hv;
                    *(__nv_bfloat162*)&ob[rb + 64 + d] = lv;
                } else {   // mode 3
                    __nv_bfloat16* ob = (__nv_bfloat16*)outp;
                    __nv_bfloat16 h0 = __float2bfloat16(v0);
                    ob[(size_t)col * ldc + row] = h0;
                    ob[(size_t)col * ldc + oLo + row] =
                        __float2bfloat16(v0 - __bfloat162float(h0));
                    __nv_bfloat16 h1 = __float2bfloat16(v1);
                    ob[(size_t)(col + 1) * ldc + row] = h1;
                    ob[(size_t)(col + 1) * ldc + oLo + row] =
                        __float2bfloat16(v1 - __bfloat162float(h1));
                }
            }
        }
}

// ---------------------------------------------------------------------------
// Conversions
// ---------------------------------------------------------------------------
__global__ __launch_bounds__(256) void wsplitT(
    const float* __restrict__ W, int K, int N, __nv_bfloat16* __restrict__ Wt)
{
    __shared__ float tile[32][33];
    int n0 = blockIdx.x * 32, k0 = blockIdx.y * 32;
    int tx = threadIdx.x, ty = threadIdx.y;
#pragma unroll
    for (int i = 0; i < 32; i += 8)
        tile[ty + i][tx] = W[(size_t)(k0 + ty + i) * N + n0 + tx];
    __syncthreads();
#pragma unroll
    for (int i = 0; i < 32; i += 8) {
        int n = n0 + ty + i, k = k0 + tx;
        float v = tile[tx][ty + i];
        __nv_bfloat16 h = __float2bfloat16(v);
        Wt[(size_t)n * 2 * K + k] = h;
        Wt[(size_t)n * 2 * K + K + k] = __float2bfloat16(v - __bfloat162float(h));
    }
}

__global__ __launch_bounds__(256) void rowsplit(
    const float* __restrict__ W, int ldw, int colOff,
    __nv_bfloat16* __restrict__ out)
{
    int i = blockIdx.x;
    int c = threadIdx.x * 4;
    float4 v = *(const float4*)&W[(size_t)i * ldw + colOff + c];
    __nv_bfloat162 h0, h1, l0, l1;
    h0.x = __float2bfloat16(v.x); h0.y = __float2bfloat16(v.y);
    h1.x = __float2bfloat16(v.z); h1.y = __float2bfloat16(v.w);
    l0.x = __float2bfloat16(v.x - __bfloat162float(h0.x));
    l0.y = __float2bfloat16(v.y - __bfloat162float(h0.y));
    l1.x = __float2bfloat16(v.z - __bfloat162float(h1.x));
    l1.y = __float2bfloat16(v.w - __bfloat162float(h1.y));
    __nv_bfloat16* o = out + (size_t)i * 2048;
    *(__nv_bfloat162*)&o[c] = h0;
    *(__nv_bfloat162*)&o[c + 2] = h1;
    *(__nv_bfloat162*)&o[1024 + c] = l0;
    *(__nv_bfloat162*)&o[1024 + c + 2] = l1;
}

__global__ __launch_bounds__(256) void xsplit(
    const float* __restrict__ x, __nv_bfloat16* __restrict__ xs)
{
    size_t i = (size_t)blockIdx.x * 256 + threadIdx.x;
    size_t r = i >> 8;
    int c = (int)(i & 255) * 4;
    float4 v = *(const float4*)&x[r * 1024 + c];
    __nv_bfloat162 h0, h1, l0, l1;
    h0.x = __float2bfloat16(v.x); h0.y = __float2bfloat16(v.y);
    h1.x = __float2bfloat16(v.z); h1.y = __float2bfloat16(v.w);
    l0.x = __float2bfloat16(v.x - __bfloat162float(h0.x));
    l0.y = __float2bfloat16(v.y - __bfloat162float(h0.y));
    l1.x = __float2bfloat16(v.z - __bfloat162float(h1.x));
    l1.y = __float2bfloat16(v.w - __bfloat162float(h1.y));
    *(__nv_bfloat162*)&xs[r * 2048 + c] = h0;
    *(__nv_bfloat162*)&xs[r * 2048 + c + 2] = h1;
    *(__nv_bfloat162*)&xs[r * 2048 + 1024 + c] = l0;
    *(__nv_bfloat162*)&xs[r * 2048 + 1024 + c + 2] = l1;
}

__global__ __launch_bounds__(1024) void biasfold3(
    const float* __restrict__ bc,
    const float* __restrict__ Wq, const float* __restrict__ Wk,
    const float* __restrict__ Wv,
    const float* __restrict__ bq, const float* __restrict__ bk,
    const float* __restrict__ bv,
    float* __restrict__ out)
{
    int s = blockIdx.x;
    int n = threadIdx.x;
    const float* W  = (s == 0) ? Wq : (s == 1) ? Wk : Wv;
    const float* b2 = (s == 0) ? bq : (s == 1) ? bk : bv;
    const float* bs = bc + s * 1024;
    float a0 = 0.f, a1 = 0.f, a2 = 0.f, a3 = 0.f;
#pragma unroll 1
    for (int m = 0; m < 1024; m += 16) {
#pragma unroll
        for (int j = 0; j < 16; j++) {
            float w = W[(size_t)(m + j) * 1024 + n];
            float bb = bs[m + j];
            if ((j & 3) == 0) a0 = fmaf(bb, w, a0);
            else if ((j & 3) == 1) a1 = fmaf(bb, w, a1);
            else if ((j & 3) == 2) a2 = fmaf(bb, w, a2);
            else a3 = fmaf(bb, w, a3);
        }
    }
    out[s * 1024 + n] = a0 + a1 + a2 + a3 + b2[n];
}

// ---------------------------------------------------------------------------
// HMMA dilated attention, ALL branches in one launch.
// grid (4, 14, 32): y<8 branch0, y<12 branch1, else branch2.
// m-tile order reversed so heaviest tiles schedule first.
// ---------------------------------------------------------------------------
#define AP 272
#define ATTN2_SMEM (3 * 128 * AP)   // 104448 B

__global__ void __launch_bounds__(256, 1) attn2(
    const __nv_bfloat16* __restrict__ qkvb,
    float* __restrict__ o0, float* __restrict__ l0,
    float* __restrict__ o1, float* __restrict__ l1,
    float* __restrict__ o2, float* __restrict__ l2)
{
    extern __shared__ __align__(128) char sm2[];
    const uint32_t Qs = smem_u32(sm2);
    const uint32_t Ks = Qs + 128 * AP;
    const uint32_t Vt = Ks + 128 * AP;

    const int tid = threadIdx.x;
    const int warp = tid >> 5, lane = tid & 31;
    const int m0 = (3 - blockIdx.x) * 128;   // heavy tiles first
    const int y = blockIdx.y;
    int w, r, seg, Tr;
    float *obr, *lbr;
    if (y < 8)       { w = 512;  r = 1; seg = y;      Tr = 4096; obr = o0; lbr = l0; }
    else if (y < 12) { w = 1024; r = 2; seg = y - 8;  Tr = 2048; obr = o1; lbr = l1; }
    else             { w = 2048; r = 4; seg = y - 12; Tr = 1024; obr = o2; lbr = l2; }
    const int bh = blockIdx.z;
    const int h = bh & 15;
    const int off = h & (r - 1);
    const int segbase = seg * w + off;
    const __nv_bfloat16* qb = qkvb;
    const __nv_bfloat16* kb = qkvb + (size_t)32 * T_ * 128;
    const __nv_bfloat16* vb = qkvb + (size_t)64 * T_ * 128;
    const size_t bhbase = (size_t)bh * T_;

    // Q tile (once)
#pragma unroll
    for (int j = 0; j < 8; j++) {
        int f = tid + j * 256;
        int row = f >> 4, si = f & 15;
        const __nv_bfloat16* g =
            qb + (bhbase + segbase + (size_t)(m0 + row) * r) * 128 + si * 8;
        cp16(Qs + row * AP + si * 16, g);
    }
    asm volatile("cp.async.commit_group;\n" ::: "memory");

    float S[16][4];
    float O[8][4];
#pragma unroll
    for (int i = 0; i < 8; i++)
#pragma unroll
        for (int j2 = 0; j2 < 4; j2++) O[i][j2] = 0.f;
    float ml[2] = {-1e30f, -1e30f};
    float ll[2] = {0.f, 0.f};

    const int ntile = (m0 >> 7) + 1;
#pragma unroll 1
    for (int nt = 0; nt < ntile; nt++) {
        const int n0 = nt * 128;
        if (nt > 0) __syncthreads();

        // K tile
#pragma unroll
        for (int j = 0; j < 8; j++) {
            int f = tid + j * 256;
            int row = f >> 4, si = f & 15;
            const __nv_bfloat16* g =
                kb + (bhbase + segbase + (size_t)(n0 + row) * r) * 128 + si * 8;
            cp16(Ks + row * AP + si * 16, g);
        }
        asm volatile("cp.async.commit_group;\n" ::: "memory");

        // V tile: load rows, write transposed (d-major) to smem
#pragma unroll
        for (int j = 0; j < 8; j++) {
            int f = tid + j * 256;
            int key = f & 127, si = f >> 7;
            const uint4 vv = *(const uint4*)(
                vb + (bhbase + segbase + (size_t)(n0 + key) * r) * 128 + si * 8);
            const uint16_t* pv = (const uint16_t*)&vv;
#pragma unroll
            for (int e = 0; e < 8; e++)
                asm volatile("st.shared.u16 [%0], %1;" ::
                             "r"(Vt + (si * 8 + e) * AP + key * 2), "h"(pv[e]));
        }
        asm volatile("cp.async.wait_group 0;\n" ::: "memory");
        __syncthreads();

        // ---- S = Q K^T, 3-term split ----
#pragma unroll
        for (int t = 0; t < 16; t++)
#pragma unroll
            for (int j2 = 0; j2 < 4; j2++) S[t][j2] = 0.f;

#pragma unroll
        for (int kk = 0; kk < 4; kk++) {
            uint32_t qh[4], qlo[4];
            uint32_t abase = Qs + (uint32_t)(warp * 16 + (lane & 15)) * AP +
                             ((lane >> 4) << 4) + kk * 32;
            ldm4(qh, abase);
            ldm4(qlo, abase + 128);
#pragma unroll
            for (int hf = 0; hf < 2; hf++) {
                uint32_t kh[4][4], kl2[4][4];
#pragma unroll
                for (int nb = 0; nb < 4; nb++) {
                    int rowk = hf * 64 + nb * 16 + ((lane >> 4) & 1) * 8 + (lane & 7);
                    uint32_t kaddr = Ks + (uint32_t)rowk * AP +
                                     (((lane >> 3) & 1) << 4) + kk * 32;
                    ldm4(kh[nb], kaddr);
                    ldm4(kl2[nb], kaddr + 128);
                }
#pragma unroll
                for (int nn = 0; nn < 8; nn++) {
                    int t = hf * 8 + nn;
                    const uint32_t* bh2 = &kh[nn >> 1][(nn & 1) * 2];
                    const uint32_t* bl2 = &kl2[nn >> 1][(nn & 1) * 2];
                    mma16816(S[t], qh, bh2);
                    mma16816(S[t], qlo, bh2);
                    mma16816(S[t], qh, bl2);
                }
            }
        }

        // Causal mask on the diagonal tile
        if (n0 == m0) {
#pragma unroll
            for (int t = 0; t < 16; t++) {
                int colb = n0 + t * 8 + (lane & 3) * 2;
#pragma unroll
                for (int j2 = 0; j2 < 4; j2++) {
                    int rowg = m0 + warp * 16 + (lane >> 2) + (j2 >> 1) * 8;
                    if (colb + (j2 & 1) > rowg) S[t][j2] = -1e30f;
                }
            }
        }

        // Online softmax (warp-local rows; quad shuffle reduce)
#pragma unroll
        for (int rr = 0; rr < 2; rr++) {
            float vmax = -1e30f;
#pragma unroll
            for (int t = 0; t < 16; t++) {
                vmax = fmaxf(vmax, S[t][rr * 2 + 0]);
                vmax = fmaxf(vmax, S[t][rr * 2 + 1]);
            }
            vmax = fmaxf(vmax, __shfl_xor_sync(0xffffffffu, vmax, 1));
            vmax = fmaxf(vmax, __shfl_xor_sync(0xffffffffu, vmax, 2));
            float mn = fmaxf(ml[rr], vmax);
            float alpha = __expf(ml[rr] - mn);
            ml[rr] = mn;
            float rs = 0.f;
#pragma unroll
            for (int t = 0; t < 16; t++) {
                float e0 = fexp2((S[t][rr * 2 + 0] - mn) * 1.44269504f);
                float e1 = fexp2((S[t][rr * 2 + 1] - mn) * 1.44269504f);
                S[t][rr * 2 + 0] = e0;
                S[t][rr * 2 + 1] = e1;
                rs += e0 + e1;
            }
            rs += __shfl_xor_sync(0xffffffffu, rs, 1);
            rs += __shfl_xor_sync(0xffffffffu, rs, 2);
            ll[rr] = ll[rr] * alpha + rs;
#pragma unroll
            for (int nn = 0; nn < 8; nn++) {
                O[nn][rr * 2 + 0] *= alpha;
                O[nn][rr * 2 + 1] *= alpha;
            }
        }

        // ---- O += P V, 3-term split; P fed straight from S registers ----
#pragma unroll
        for (int ks = 0; ks < 8; ks++) {
            uint32_t ph[4], pl[4];
#pragma unroll
            for (int q2 = 0; q2 < 4; q2++) {
                int t = ks * 2 + (q2 >> 1);
                float a = S[t][(q2 & 1) * 2 + 0];
                float b = S[t][(q2 & 1) * 2 + 1];
                __nv_bfloat162 hv;
                hv.x = __float2bfloat16(a);
                hv.y = __float2bfloat16(b);
                ph[q2] = *(uint32_t*)&hv;
                __nv_bfloat162 lv;
                lv.x = __float2bfloat16(a - __bfloat162float(hv.x));
                lv.y = __float2bfloat16(b - __bfloat162float(hv.y));
                pl[q2] = *(uint32_t*)&lv;
            }
            uint32_t vh[4][4], vl2[4][4];
#pragma unroll
            for (int nb = 0; nb < 4; nb++) {
                int rowd = nb * 16 + ((lane >> 4) & 1) * 8 + (lane & 7);
                uint32_t vaddr = Vt + (uint32_t)rowd * AP +
                                 (((lane >> 3) & 1) << 4) + ks * 32;
                ldm4(vh[nb], vaddr);
                ldm4(vl2[nb], vaddr + 64 * AP);
            }
#pragma unroll
            for (int nn = 0; nn < 8; nn++) {
                const uint32_t* bh2 = &vh[nn >> 1][(nn & 1) * 2];
                const uint32_t* bl2 = &vl2[nn >> 1][(nn & 1) * 2];
                mma16816(O[nn], ph, bh2);
                mma16816(O[nn], pl, bh2);
                mma16816(O[nn], ph, bl2);
            }
        }
    }

    // Epilogue
#pragma unroll
    for (int rr = 0; rr < 2; rr++) {
        float inv = 1.f / ll[rr];
        size_t orow = (size_t)bh * Tr + seg * 512 + m0 + warp * 16 +
                      (lane >> 2) + rr * 8;
#pragma unroll
        for (int nn = 0; nn < 8; nn++) {
            float2 o2;
            o2.x = O[nn][rr * 2 + 0] * inv;
            o2.y = O[nn][rr * 2 + 1] * inv;
            *(float2*)&obr[orow * D_ + nn * 8 + (lane & 3) * 2] = o2;
        }
        if ((lane & 3) == 0) lbr[orow] = ml[rr] + logf(ll[rr]);
    }
}

// ---------------------------------------------------------------------------
// Combine branches with LSE weights; emit split bf16 y2 [8192, 2048]
// ---------------------------------------------------------------------------
__global__ __launch_bounds__(128) void combine_kernel(
    const float* __restrict__ o0, const float* __restrict__ o1,
    const float* __restrict__ o2,
    const float* __restrict__ l0, const float* __restrict__ l1,
    const float* __restrict__ l2,
    __nv_bfloat16* __restrict__ y2)
{
    int rowid = blockIdx.x * 128 + threadIdx.x;
    int bh = rowid >> 12;
    int t = rowid & 4095;
    int h = bh & (H_ - 1);
    int b = bh >> 4;

    float L0 = l0[(size_t)bh * 4096 + t];
    bool c1 = ((t & 1) == (h & 1));
    bool c2 = ((t & 3) == (h & 3));
    size_t i1 = (size_t)bh * 2048 + ((size_t)(t >> 10) << 9) + ((t & 1023) >> 1);
    size_t i2 = (size_t)bh * 1024 + ((size_t)(t >> 11) << 9) + ((t & 2047) >> 2);
    float L1 = c1 ? l1[i1] : -1e30f;
    float L2 = c2 ? l2[i2] : -1e30f;
    float m = fmaxf(L0, fmaxf(L1, L2));
    float w0 = __expf(L0 - m);
    float w1 = c1 ? __expf(L1 - m) : 0.f;
    float w2 = c2 ? __expf(L2 - m) : 0.f;
    float inv = 1.f / (w0 + w1 + w2);
    w0 *= inv; w1 *= inv; w2 *= inv;

    const float* p0 = o0 + ((size_t)bh * 4096 + t) * D_;
    const float* p1 = o1 + i1 * D_;
    const float* p2 = o2 + i2 * D_;
    size_t ybase = (size_t)(b * 4096 + t) * 2048 + h * D_;

#pragma unroll
    for (int d = 0; d < 64; d += 4) {
        float4 a0 = *(const float4*)&p0[d];
        float4 res = make_float4(w0 * a0.x, w0 * a0.y, w0 * a0.z, w0 * a0.w);
        if (c1) {
            float4 a1 = *(const float4*)&p1[d];
            res.x += w1 * a1.x; res.y += w1 * a1.y;
            res.z += w1 * a1.z; res.w += w1 * a1.w;
        }
        if (c2) {
            float4 a2 = *(const float4*)&p2[d];
            res.x += w2 * a2.x; res.y += w2 * a2.y;
            res.z += w2 * a2.z; res.w += w2 * a2.w;
        }
        __nv_bfloat162 h0, h1, lo0, lo1;
        h0.x = __float2bfloat16(res.x); h0.y = __float2bfloat16(res.y);
        h1.x = __float2bfloat16(res.z); h1.y = __float2bfloat16(res.w);
        lo0.x = __float2bfloat16(res.x - __bfloat162float(h0.x));
        lo0.y = __float2bfloat16(res.y - __bfloat162float(h0.y));
        lo1.x = __float2bfloat16(res.z - __bfloat162float(h1.x));
        lo1.y = __float2bfloat16(res.w - __bfloat162float(h1.y));
        *(__nv_bfloat162*)&y2[ybase + d] = h0;
        *(__nv_bfloat162*)&y2[ybase + d + 2] = h1;
        *(__nv_bfloat162*)&y2[ybase + 1024 + d] = lo0;
        *(__nv_bfloat162*)&y2[ybase + 1024 + d + 2] = lo1;
    }
}

// ---------------------------------------------------------------------------
// Launch
// ---------------------------------------------------------------------------
extern "C" void kernel_launch(void* const* d_in, const int* in_sizes, int n_in,
                              void* d_out, int out_size)
{
    (void)in_sizes; (void)n_in; (void)out_size;
    const float* x        = (const float*)d_in[0];
    const float* c_attn_w = (const float*)d_in[1];
    const float* c_attn_b = (const float*)d_in[2];
    const float* q_w      = (const float*)d_in[3];
    const float* q_b      = (const float*)d_in[4];
    const float* k_w      = (const float*)d_in[5];
    const float* k_b      = (const float*)d_in[6];
    const float* v_w      = (const float*)d_in[7];
    const float* v_b      = (const float*)d_in[8];
    const float* o_w      = (const float*)d_in[9];
    const float* o_b      = (const float*)d_in[10];
    float* out = (float*)d_out;

    __nv_bfloat16 *xs, *wqkv, *wo, *wcr, *wf, *y2, *qkvb;
    float *bf, *zero, *o0, *o1, *o2, *l0, *l1, *l2;
    cudaGetSymbolAddress((void**)&xs,   g_xs);
    cudaGetSymbolAddress((void**)&wqkv, g_wqkv);
    cudaGetSymbolAddress((void**)&wo,   g_wo);
    cudaGetSymbolAddress((void**)&wcr,  g_wcr);
    cudaGetSymbolAddress((void**)&wf,   g_wf);
    cudaGetSymbolAddress((void**)&bf,   g_bf);
    cudaGetSymbolAddress((void**)&zero, g_zero);
    cudaGetSymbolAddress((void**)&qkvb, g_qkvb);
    cudaGetSymbolAddress((void**)&y2,   g_y2);
    cudaGetSymbolAddress((void**)&o0,   g_o0);
    cudaGetSymbolAddress((void**)&o1,   g_o1);
    cudaGetSymbolAddress((void**)&o2,   g_o2);
    cudaGetSymbolAddress((void**)&l0,   g_l0);
    cudaGetSymbolAddress((void**)&l1,   g_l1);
    cudaGetSymbolAddress((void**)&l2,   g_l2);

    cudaFuncSetAttribute(gemm_mma, cudaFuncAttributeMaxDynamicSharedMemorySize,
                         GEMM_SMEM);
    cudaFuncSetAttribute(attn2, cudaFuncAttributeMaxDynamicSharedMemorySize,
                         ATTN2_SMEM);

    const size_t WSL = (size_t)1024 * 2048 * sizeof(__nv_bfloat16);  // 4 MB

    // 0) conversions
    xsplit<<<8192, 256>>>(x, xs);
    wsplitT<<<dim3(32, 32), dim3(32, 8)>>>(q_w, 1024, 1024, wqkv);
    wsplitT<<<dim3(32, 32), dim3(32, 8)>>>(k_w, 1024, 1024,
                                           wqkv + (size_t)1024 * 2048);
    wsplitT<<<dim3(32, 32), dim3(32, 8)>>>(v_w, 1024, 1024,
                                           wqkv + (size_t)2048 * 2048);
    wsplitT<<<dim3(32, 32), dim3(32, 8)>>>(o_w, 1024, 1024, wo);
    rowsplit<<<1024, 256>>>(c_attn_w, 3072, 0,    wcr);
    rowsplit<<<1024, 256>>>(c_attn_w, 3072, 1024, wcr + (size_t)1024 * 2048);
    rowsplit<<<1024, 256>>>(c_attn_w, 3072, 2048, wcr + (size_t)2048 * 2048);
    biasfold3<<<3, 1024>>>(c_attn_b, q_w, k_w, v_w, q_b, k_b, v_b, bf);

    // 1) fused-weight prep (single z-batched launch, one wave)
    gemm_mma<<<dim3(8, 8, 3), 256, GEMM_SMEM>>>(
        wcr, 2048, 0, 1024, wqkv, 2048, 0, 1024,
        zero, wf, 2048, 1024, 32, 3, 1.f, WSL, WSL, WSL);

    // 2) merged projection: q/k/v = x @ Wf + bf -> split bf16 [s][bh][t][hi|lo]
    gemm_mma<<<dim3(24, 64), 256, GEMM_SMEM>>>(
        xs, 2048, 0, 1024, wf, 2048, 0, 1024, bf,
        qkvb, 0, 0, 32, 1, 0.125f, 0, 0, 0);

    // 3) HMMA dilated attention, all branches in one launch
    attn2<<<dim3(4, 14, 32), 256, ATTN2_SMEM>>>(qkvb, o0, l0, o1, l1, o2, l2);

    // 4) combine -> split bf16 y2
    combine_kernel<<<dim3(B_ * H_ * T_ / 128), 128>>>(o0, o1, o2, l0, l1, l2,
                                                      y2);
    // 5) out = y @ o_w + o_b
    gemm_mma<<<dim3(8, 64), 256, GEMM_SMEM>>>(
        y2, 2048, 0, 1024, wo, 2048, 0, 1024, o_b,
        out, 1024, 0, 32, 0, 1.f, 0, 0, 0);
}